// round 3
// baseline (speedup 1.0000x reference)
#include <cuda_runtime.h>
#include <stdint.h>
#include <math.h>

// ---------------- problem constants (fixed shapes) ----------------
#define B_    2
#define H_    16
#define NTOK  8192
#define D_    128
#define G_    8
#define P_    1024
#define MK_   34
#define S_    (G_*MK_)        // 272
#define BH_   (B_*H_)         // 32

#define SCALE_F 0.08838834764831843f   // 128^-0.5
#define LN8_F   2.0794415416798357f
#define TINY_F  1.17549435e-38f
#define EPS_F   1.1920929e-07f

// ---------------- scratch (device globals; no allocations) ----------------
__device__ __align__(16) float g_qrep [BH_*P_*D_];
__device__ __align__(16) float g_krep [BH_*P_*D_];
__device__ __align__(16) float g_vmean[BH_*P_*D_];
__device__ __align__(16) float g_attn1[BH_*P_*D_];
__device__ __align__(16) float g_adel [BH_*P_*D_];
__device__ __align__(16) float g_aadd [BH_*P_*D_];
__device__ float g_lse1[BH_*P_];
__device__ float g_ldel[BH_*P_];
__device__ float g_ladd[BH_*P_];
__device__ float g_score_k[BH_*G_*P_];
__device__ float g_score_q[BH_*G_*P_];
__device__ int   g_kidx[BH_*G_*MK_];
__device__ int   g_qidx[BH_*G_*MK_];
__device__ __align__(16) float g_ksub   [BH_*S_*D_];
__device__ __align__(16) float g_krepsub[BH_*S_*D_];
__device__ __align__(16) float g_vsub   [BH_*S_*D_];
__device__ __align__(16) float g_qsub   [BH_*S_*D_];
__device__ __align__(16) float g_a2     [BH_*S_*D_];
__device__ float g_l2[BH_*S_];

// ---------------- JAX threefry2x32 (20 rounds) ----------------
__device__ __forceinline__ void threefry2x32(uint32_t k0, uint32_t k1,
                                             uint32_t x0, uint32_t x1,
                                             uint32_t& o0, uint32_t& o1) {
  uint32_t k2 = k0 ^ k1 ^ 0x1BD11BDAu;
  x0 += k0; x1 += k1;
#define TFR(r) { x0 += x1; x1 = (x1 << (r)) | (x1 >> (32 - (r))); x1 ^= x0; }
  TFR(13) TFR(15) TFR(26) TFR(6)   x0 += k1; x1 += k2 + 1u;
  TFR(17) TFR(29) TFR(16) TFR(24)  x0 += k2; x1 += k0 + 2u;
  TFR(13) TFR(15) TFR(26) TFR(6)   x0 += k0; x1 += k1 + 3u;
  TFR(17) TFR(29) TFR(16) TFR(24)  x0 += k1; x1 += k2 + 4u;
  TFR(13) TFR(15) TFR(26) TFR(6)   x0 += k2; x1 += k0 + 5u;
#undef TFR
  o0 = x0; o1 = x1;
}

// ---------------- 1) group means: q_rep, k_rep, v_mean ----------------
__global__ void __launch_bounds__(256) means_kernel(const float* __restrict__ q,
                                                    const float* __restrict__ k,
                                                    const float* __restrict__ v) {
  int idx = blockIdx.x * 256 + threadIdx.x;          // over BH_*P_*32 float4
  int bh  = idx / (P_*32);
  int rem = idx - bh * (P_*32);
  const float4* q4 = (const float4*)q + (size_t)bh*NTOK*32 + rem;
  const float4* k4 = (const float4*)k + (size_t)bh*NTOK*32 + rem;
  const float4* v4 = (const float4*)v + (size_t)bh*NTOK*32 + rem;
  float4 sq = make_float4(0,0,0,0), sk = sq, sv = sq;
#pragma unroll
  for (int g = 0; g < G_; g++) {
    float4 a = q4[(size_t)g*P_*32]; sq.x+=a.x; sq.y+=a.y; sq.z+=a.z; sq.w+=a.w;
    float4 b = k4[(size_t)g*P_*32]; sk.x+=b.x; sk.y+=b.y; sk.z+=b.z; sk.w+=b.w;
    float4 c = v4[(size_t)g*P_*32]; sv.x+=c.x; sv.y+=c.y; sv.z+=c.z; sv.w+=c.w;
  }
  const float s = 1.0f / G_;
  sq.x*=s; sq.y*=s; sq.z*=s; sq.w*=s;
  sk.x*=s; sk.y*=s; sk.z*=s; sk.w*=s;
  sv.x*=s; sv.y*=s; sv.z*=s; sv.w*=s;
  ((float4*)g_qrep )[idx] = sq;
  ((float4*)g_krep )[idx] = sk;
  ((float4*)g_vmean)[idx] = sv;
}

// ---------------- 2) residual-norm + gumbel scores ----------------
__global__ void __launch_bounds__(256) scores_kernel(const float* __restrict__ q,
                                                     const float* __restrict__ k) {
  unsigned wi = (blockIdx.x * 256u + threadIdx.x) >> 5;   // warp per row
  int lane = threadIdx.x & 31;
  const unsigned RT = (unsigned)(BH_*G_*P_);              // 262144
  int t = wi >= RT;                      // 0: key stream (rk), 1: query (rq)
  unsigned r  = t ? wi - RT : wi;
  unsigned bh = r >> 13;
  unsigned g  = (r >> 10) & 7u;
  unsigned j  = r & 1023u;
  const float* x  = (t ? q : k)           + (((size_t)bh*NTOK + g*P_ + j) << 7);
  const float* rp = (t ? g_qrep : g_krep) + (((size_t)bh*P_ + j) << 7);
  float4 a = *(const float4*)(x  + lane*4);
  float4 b = *(const float4*)(rp + lane*4);
  float dx=a.x-b.x, dy=a.y-b.y, dz=a.z-b.z, dw=a.w-b.w;
  float ss = dx*dx + dy*dy + dz*dz + dw*dw;
#pragma unroll
  for (int off = 16; off; off >>= 1)
    ss += __shfl_xor_sync(0xffffffffu, ss, off);
  if (lane == 0) {
    uint32_t rk0, rk1, o0, o1;
    threefry2x32(0u, 42u, 0u, (uint32_t)t, rk0, rk1);  // fold-like split of key(42)
    threefry2x32(rk0, rk1, 0u, r, o0, o1);             // partitionable random_bits
    uint32_t bits = o0 ^ o1;
    float u = __uint_as_float((bits >> 9) | 0x3f800000u) - 1.0f;
    if (u <= 0.0f) u = TINY_F;
    float gum = -logf(-logf(u));
    float score = logf(sqrtf(ss) * 100.0f + EPS_F) + gum;
    (t ? g_score_q : g_score_k)[r] = score;
  }
}

// ---------------- 3) top-34 per group of 1024 ----------------
__global__ void __launch_bounds__(256) topk_kernel() {
  int grp = blockIdx.x;       // 0..255 (bh*8+g)
  int t   = blockIdx.y;       // 0 key, 1 query
  float* sc = (t ? g_score_q : g_score_k) + (size_t)grp * P_;
  int*  out = (t ? g_qidx    : g_kidx   ) + (size_t)grp * MK_;
  __shared__ float sv[1024];
  __shared__ float rv[256];
  __shared__ int   ri[256];
  int tid = threadIdx.x;
#pragma unroll
  for (int r = 0; r < 4; r++) sv[tid + 256*r] = sc[tid + 256*r];
  __syncthreads();
  for (int it = 0; it < MK_; it++) {
    float bv = -INFINITY; int bi = 0x7fffffff;
#pragma unroll
    for (int r = 0; r < 4; r++) {
      int i = tid + 256*r;
      float vv = sv[i];
      if (vv > bv || (vv == bv && i < bi)) { bv = vv; bi = i; }
    }
    rv[tid] = bv; ri[tid] = bi;
    __syncthreads();
    for (int s = 128; s; s >>= 1) {
      if (tid < s) {
        float vv = rv[tid+s]; int i2 = ri[tid+s];
        if (vv > rv[tid] || (vv == rv[tid] && i2 < ri[tid])) { rv[tid]=vv; ri[tid]=i2; }
      }
      __syncthreads();
    }
    if (tid == 0) { out[it] = ri[0]; sv[ri[0]] = -INFINITY; }
    __syncthreads();
  }
}

// ---------------- 4) gathers ----------------
__global__ void __launch_bounds__(256) gather_kernel(const float* __restrict__ q,
                                                     const float* __restrict__ k,
                                                     const float* __restrict__ v) {
  unsigned wi = (blockIdx.x * 256u + threadIdx.x) >> 5;
  int lane = threadIdx.x & 31;
  if (wi >= (unsigned)(BH_*S_)) return;
  int bh = wi / S_;
  int rr = wi % S_;
  int g = rr / MK_, tt = rr % MK_;
  int kj = g_kidx[(bh*G_+g)*MK_+tt];
  int qj = g_qidx[(bh*G_+g)*MK_+tt];
  size_t srck = ((size_t)bh*NTOK + g*P_ + kj) << 7;
  size_t srcq = ((size_t)bh*NTOK + g*P_ + qj) << 7;
  size_t dst  = ((size_t)wi << 7) + lane*4;
  *(float4*)(g_ksub    + dst) = *(const float4*)(k + srck + lane*4);
  *(float4*)(g_vsub    + dst) = *(const float4*)(v + srck + lane*4);
  *(float4*)(g_krepsub + dst) = *(const float4*)(g_krep + (((size_t)bh*P_ + kj) << 7) + lane*4);
  *(float4*)(g_qsub    + dst) = *(const float4*)(q + srcq + lane*4);
}

// ---------------- 5) generic flash attention (fp32) ----------------
// modes: 0 = p0 (qrep x krep -> attn1/lse1)
//        1 = p1-del (qrep x krepsub/vsub -> adel/ldel)
//        2 = p1-add (qrep x ksub/vsub -> aadd/ladd)
//        3 = p2 (qsub x key/value -> a2/l2)
__global__ void __launch_bounds__(256) attn_kernel(int mode,
                                                   const float* __restrict__ kx,
                                                   const float* __restrict__ vx) {
  __shared__ float4 Kc[32*33];        // [chunk][key] padded
  __shared__ float4 Vr[32*33];        // [key][chunk] padded
  __shared__ float4 qsm[8*33];
  const float *Q, *K, *V; float *O, *L; int nq, nk; size_t qstr, kstr;
  if (mode == 0) { Q=g_qrep; K=g_krep;    V=g_vmean; O=g_attn1; L=g_lse1; nq=P_; nk=P_;   qstr=P_*D_;  kstr=P_*D_; }
  else if (mode == 1) { Q=g_qrep; K=g_krepsub; V=g_vsub; O=g_adel; L=g_ldel; nq=P_; nk=S_; qstr=P_*D_; kstr=(size_t)S_*D_; }
  else if (mode == 2) { Q=g_qrep; K=g_ksub;    V=g_vsub; O=g_aadd; L=g_ladd; nq=P_; nk=S_; qstr=P_*D_; kstr=(size_t)S_*D_; }
  else { Q=g_qsub; K=kx; V=vx; O=g_a2; L=g_l2; nq=S_; nk=NTOK; qstr=(size_t)S_*D_; kstr=(size_t)NTOK*D_; }

  int bh = blockIdx.y;
  Q += (size_t)bh*qstr; K += (size_t)bh*kstr; V += (size_t)bh*kstr;
  O += (size_t)bh*qstr; L += (size_t)bh*nq;
  int w = threadIdx.x >> 5, lane = threadIdx.x & 31;
  int row = blockIdx.x*8 + w;

  float4 q4 = *(const float4*)(Q + (size_t)row*D_ + lane*4);
  qsm[w*33 + lane] = q4;
  float4 o = make_float4(0,0,0,0);
  float m = -INFINITY, sacc = 0.0f;
  int ntile = (nk + 31) >> 5;
  for (int tile = 0; tile < ntile; tile++) {
    int j0 = tile << 5;
#pragma unroll
    for (int r = 0; r < 4; r++) {
      int j = w*4 + r;
      int gj = j0 + j;
      float4 kv = make_float4(0,0,0,0), vv = kv;
      if (gj < nk) {
        kv = *(const float4*)(K + (size_t)gj*D_ + lane*4);
        vv = *(const float4*)(V + (size_t)gj*D_ + lane*4);
      }
      Kc[lane*33 + j] = kv;
      Vr[j*33 + lane] = vv;
    }
    __syncthreads();
    float s = 0.0f;
    const float4* qr = &qsm[w*33];
#pragma unroll
    for (int c = 0; c < 32; c++) {
      float4 qv = qr[c];
      float4 kv = Kc[c*33 + lane];
      s += qv.x*kv.x; s += qv.y*kv.y; s += qv.z*kv.z; s += qv.w*kv.w;
    }
    s *= SCALE_F;
    if (j0 + lane >= nk) s = -INFINITY;
    float tmax = s;
#pragma unroll
    for (int off = 16; off; off >>= 1)
      tmax = fmaxf(tmax, __shfl_xor_sync(0xffffffffu, tmax, off));
    float mnew = fmaxf(m, tmax);
    float p = __expf(s - mnew);
    float corr = __expf(m - mnew);
    float psum = p;
#pragma unroll
    for (int off = 16; off; off >>= 1)
      psum += __shfl_xor_sync(0xffffffffu, psum, off);
    sacc = sacc*corr + psum;
    o.x *= corr; o.y *= corr; o.z *= corr; o.w *= corr;
    m = mnew;
#pragma unroll
    for (int j = 0; j < 32; j++) {
      float pv = __shfl_sync(0xffffffffu, p, j);
      float4 vv = Vr[j*33 + lane];
      o.x += pv*vv.x; o.y += pv*vv.y; o.z += pv*vv.z; o.w += pv*vv.w;
    }
    __syncthreads();
  }
  float inv = 1.0f / sacc;
  o.x*=inv; o.y*=inv; o.z*=inv; o.w*=inv;
  *(float4*)(O + (size_t)row*D_ + lane*4) = o;
  if (lane == 0) L[row] = m + logf(sacc);
}

// ---------------- 6) p1 combine + broadcast write ----------------
__global__ void __launch_bounds__(256) combine_kernel(float* __restrict__ out, int has_lse) {
  unsigned wi = (blockIdx.x * 256u + threadIdx.x) >> 5;  // 32768 rows
  int lane = threadIdx.x & 31;
  int bh = wi >> 10, j = wi & 1023;
  float l1 = g_lse1[wi] + LN8_F;
  float ld = g_ldel[wi];
  float la = g_ladd[wi];
  float c1 = expf(ld - l1);
  float inv1 = 1.0f / (1.0f - c1);
  float lp1 = l1 + log1pf(-c1);
  float c2 = 1.0f / (1.0f + expf(la - lp1));
  float lse = fmaxf(lp1, la) + log1pf(expf(-fabsf(lp1 - la)));
  size_t off = ((size_t)wi << 7) + lane*4;
  float4 a0 = *(const float4*)(g_attn1 + off);
  float4 ad = *(const float4*)(g_adel + off);
  float4 aa = *(const float4*)(g_aadd + off);
  float4 r;
  float c2b = 1.0f - c2;
  r.x = c2*((a0.x - c1*ad.x)*inv1) + c2b*aa.x;
  r.y = c2*((a0.y - c1*ad.y)*inv1) + c2b*aa.y;
  r.z = c2*((a0.z - c1*ad.z)*inv1) + c2b*aa.z;
  r.w = c2*((a0.w - c1*ad.w)*inv1) + c2b*aa.w;
  float* outl = out + (size_t)BH_*NTOK*D_;
#pragma unroll
  for (int g = 0; g < G_; g++) {
    size_t orow = (size_t)bh*NTOK + g*P_ + j;
    *(float4*)(out + (orow << 7) + lane*4) = r;
    if (lane == 0 && has_lse) outl[orow] = lse;
  }
}

// ---------------- 7) p2 scatter ----------------
__global__ void __launch_bounds__(256) scatter_kernel(float* __restrict__ out, int has_lse) {
  unsigned wi = (blockIdx.x * 256u + threadIdx.x) >> 5;
  int lane = threadIdx.x & 31;
  if (wi >= (unsigned)(BH_*S_)) return;
  int bh = wi / S_;
  int rr = wi % S_;
  int g = rr / MK_, tt = rr % MK_;
  int qj = g_qidx[(bh*G_+g)*MK_+tt];
  size_t orow = (size_t)bh*NTOK + g*P_ + qj;
  float4 a = *(const float4*)(g_a2 + ((size_t)wi << 7) + lane*4);
  *(float4*)(out + (orow << 7) + lane*4) = a;
  if (lane == 0 && has_lse) out[(size_t)BH_*NTOK*D_ + orow] = g_l2[wi];
}

// ---------------- launch ----------------
extern "C" void kernel_launch(void* const* d_in, const int* in_sizes, int n_in,
                              void* d_out, int out_size) {
  const float* q = (const float*)d_in[0];
  const float* k = (const float*)d_in[1];
  const float* v = (const float*)d_in[2];
  float* out = (float*)d_out;
  int has_lse = (out_size >= BH_*NTOK*(D_ + 1)) ? 1 : 0;

  means_kernel <<<(BH_*P_*32)/256, 256>>>(q, k, v);
  scores_kernel<<<(2*BH_*G_*P_*32)/256, 256>>>(q, k);
  topk_kernel  <<<dim3(BH_*G_, 2), 256>>>();
  gather_kernel<<<(BH_*S_*32 + 255)/256, 256>>>(q, k, v);

  attn_kernel<<<dim3(P_/8, BH_), 256>>>(0, nullptr, nullptr);  // p0
  attn_kernel<<<dim3(P_/8, BH_), 256>>>(1, nullptr, nullptr);  // p1 del
  attn_kernel<<<dim3(P_/8, BH_), 256>>>(2, nullptr, nullptr);  // p1 add
  attn_kernel<<<dim3(S_/8, BH_), 256>>>(3, k, v);              // p2

  combine_kernel<<<(BH_*P_*32)/256, 256>>>(out, has_lse);
  scatter_kernel<<<(BH_*S_*32 + 255)/256, 256>>>(out, has_lse);
}

// round 4
// speedup vs baseline: 2.6598x; 2.6598x over previous
#include <cuda_runtime.h>
#include <stdint.h>
#include <math.h>

// ---------------- problem constants (fixed shapes) ----------------
#define B_    2
#define H_    16
#define NTOK  8192
#define D_    128
#define G_    8
#define P_    1024
#define MK_   34
#define S_    (G_*MK_)        // 272
#define BH_   (B_*H_)         // 32

#define SCALE_F 0.08838834764831843f   // 128^-0.5
#define LN8_F   2.0794415416798357f
#define TINY_F  1.17549435e-38f
#define EPS_F   1.1920929e-07f

// attention tiling
#define BQ 128
#define BK 64
#define QSROW 132      // Qs: [128 dims][132] (holds 128 q rows + pad)
#define KSROW 68       // Ks: [128 dims][68]  (holds 64 k + pad)
#define VSROW 132      // Vs: [64 k][132]     (holds 128 d + pad)
#define PSROW 68       // Ps: [128 q][68]     (holds 64 k + pad)
#define SMEM_FLOATS (128*QSROW + 128*KSROW + 64*VSROW + 128*PSROW)
#define SMEM_BYTES  (SMEM_FLOATS*4)

// ---------------- scratch (device globals; no allocations) ----------------
__device__ __align__(16) float g_qrep [BH_*P_*D_];
__device__ __align__(16) float g_krep [BH_*P_*D_];
__device__ __align__(16) float g_vmean[BH_*P_*D_];
__device__ __align__(16) float g_attn1[BH_*P_*D_];
__device__ __align__(16) float g_adel [BH_*P_*D_];
__device__ __align__(16) float g_aadd [BH_*P_*D_];
__device__ float g_lse1[BH_*P_];
__device__ float g_ldel[BH_*P_];
__device__ float g_ladd[BH_*P_];
__device__ float g_score_k[BH_*G_*P_];
__device__ float g_score_q[BH_*G_*P_];
__device__ int   g_kidx[BH_*G_*MK_];
__device__ int   g_qidx[BH_*G_*MK_];
__device__ __align__(16) float g_ksub   [BH_*S_*D_];
__device__ __align__(16) float g_krepsub[BH_*S_*D_];
__device__ __align__(16) float g_vsub   [BH_*S_*D_];
__device__ __align__(16) float g_qsub   [BH_*S_*D_];
__device__ __align__(16) float g_a2     [BH_*S_*D_];
__device__ float g_l2[BH_*S_];
// split-K partials: max ns*BH*qpad = 8*32*384 rows
__device__ __align__(16) float g_part_o[8*BH_*384*D_];
__device__ float g_part_m[8*BH_*384 + 1024];
__device__ float g_part_l[8*BH_*384 + 1024];

// ---------------- f32x2 packed math ----------------
typedef unsigned long long ull_t;
union F2 { float2 f; ull_t u; };
__device__ __forceinline__ void fma2(F2& d, F2 a, F2 b) {
  asm("fma.rn.f32x2 %0, %1, %2, %0;" : "+l"(d.u) : "l"(a.u), "l"(b.u));
}
__device__ __forceinline__ void mul2(F2& d, F2 a, F2 b) {
  asm("mul.rn.f32x2 %0, %1, %2;" : "=l"(d.u) : "l"(a.u), "l"(b.u));
}
__device__ __forceinline__ F2 dup2(float x) { F2 r; r.f = make_float2(x, x); return r; }
__device__ __forceinline__ F2 pk2(float x, float y) { F2 r; r.f = make_float2(x, y); return r; }

// ---------------- JAX threefry2x32 (20 rounds) ----------------
__device__ __forceinline__ void threefry2x32(uint32_t k0, uint32_t k1,
                                             uint32_t x0, uint32_t x1,
                                             uint32_t& o0, uint32_t& o1) {
  uint32_t k2 = k0 ^ k1 ^ 0x1BD11BDAu;
  x0 += k0; x1 += k1;
#define TFR(r) { x0 += x1; x1 = (x1 << (r)) | (x1 >> (32 - (r))); x1 ^= x0; }
  TFR(13) TFR(15) TFR(26) TFR(6)   x0 += k1; x1 += k2 + 1u;
  TFR(17) TFR(29) TFR(16) TFR(24)  x0 += k2; x1 += k0 + 2u;
  TFR(13) TFR(15) TFR(26) TFR(6)   x0 += k0; x1 += k1 + 3u;
  TFR(17) TFR(29) TFR(16) TFR(24)  x0 += k1; x1 += k2 + 4u;
  TFR(13) TFR(15) TFR(26) TFR(6)   x0 += k2; x1 += k0 + 5u;
#undef TFR
  o0 = x0; o1 = x1;
}

// ---------------- 1) group means ----------------
__global__ void __launch_bounds__(256) means_kernel(const float* __restrict__ q,
                                                    const float* __restrict__ k,
                                                    const float* __restrict__ v) {
  int idx = blockIdx.x * 256 + threadIdx.x;          // over BH_*P_*32 float4
  int bh  = idx / (P_*32);
  int rem = idx - bh * (P_*32);
  const float4* q4 = (const float4*)q + (size_t)bh*NTOK*32 + rem;
  const float4* k4 = (const float4*)k + (size_t)bh*NTOK*32 + rem;
  const float4* v4 = (const float4*)v + (size_t)bh*NTOK*32 + rem;
  float4 sq = make_float4(0,0,0,0), sk = sq, sv = sq;
#pragma unroll
  for (int g = 0; g < G_; g++) {
    float4 a = q4[(size_t)g*P_*32]; sq.x+=a.x; sq.y+=a.y; sq.z+=a.z; sq.w+=a.w;
    float4 b = k4[(size_t)g*P_*32]; sk.x+=b.x; sk.y+=b.y; sk.z+=b.z; sk.w+=b.w;
    float4 c = v4[(size_t)g*P_*32]; sv.x+=c.x; sv.y+=c.y; sv.z+=c.z; sv.w+=c.w;
  }
  const float s = 1.0f / G_;
  sq.x*=s; sq.y*=s; sq.z*=s; sq.w*=s;
  sk.x*=s; sk.y*=s; sk.z*=s; sk.w*=s;
  sv.x*=s; sv.y*=s; sv.z*=s; sv.w*=s;
  ((float4*)g_qrep )[idx] = sq;
  ((float4*)g_krep )[idx] = sk;
  ((float4*)g_vmean)[idx] = sv;
}

// ---------------- 2) residual-norm + gumbel scores ----------------
__global__ void __launch_bounds__(256) scores_kernel(const float* __restrict__ q,
                                                     const float* __restrict__ k) {
  unsigned wi = (blockIdx.x * 256u + threadIdx.x) >> 5;
  int lane = threadIdx.x & 31;
  const unsigned RT = (unsigned)(BH_*G_*P_);
  int t = wi >= RT;
  unsigned r  = t ? wi - RT : wi;
  unsigned bh = r >> 13;
  unsigned g  = (r >> 10) & 7u;
  unsigned j  = r & 1023u;
  const float* x  = (t ? q : k)           + (((size_t)bh*NTOK + g*P_ + j) << 7);
  const float* rp = (t ? g_qrep : g_krep) + (((size_t)bh*P_ + j) << 7);
  float4 a = *(const float4*)(x  + lane*4);
  float4 b = *(const float4*)(rp + lane*4);
  float dx=a.x-b.x, dy=a.y-b.y, dz=a.z-b.z, dw=a.w-b.w;
  float ss = dx*dx + dy*dy + dz*dz + dw*dw;
#pragma unroll
  for (int off = 16; off; off >>= 1)
    ss += __shfl_xor_sync(0xffffffffu, ss, off);
  if (lane == 0) {
    uint32_t rk0, rk1, o0, o1;
    threefry2x32(0u, 42u, 0u, (uint32_t)t, rk0, rk1);
    threefry2x32(rk0, rk1, 0u, r, o0, o1);
    uint32_t bits = o0 ^ o1;
    float u = __uint_as_float((bits >> 9) | 0x3f800000u) - 1.0f;
    if (u <= 0.0f) u = TINY_F;
    float gum = -logf(-logf(u));
    float score = logf(sqrtf(ss) * 100.0f + EPS_F) + gum;
    (t ? g_score_q : g_score_k)[r] = score;
  }
}

// ---------------- 3) top-34 per group of 1024 ----------------
__global__ void __launch_bounds__(256) topk_kernel() {
  int grp = blockIdx.x;
  int t   = blockIdx.y;
  float* sc = (t ? g_score_q : g_score_k) + (size_t)grp * P_;
  int*  out = (t ? g_qidx    : g_kidx   ) + (size_t)grp * MK_;
  __shared__ float sv[1024];
  __shared__ float rv[256];
  __shared__ int   ri[256];
  int tid = threadIdx.x;
#pragma unroll
  for (int r = 0; r < 4; r++) sv[tid + 256*r] = sc[tid + 256*r];
  __syncthreads();
  for (int it = 0; it < MK_; it++) {
    float bv = -INFINITY; int bi = 0x7fffffff;
#pragma unroll
    for (int r = 0; r < 4; r++) {
      int i = tid + 256*r;
      float vv = sv[i];
      if (vv > bv || (vv == bv && i < bi)) { bv = vv; bi = i; }
    }
    rv[tid] = bv; ri[tid] = bi;
    __syncthreads();
    for (int s = 128; s; s >>= 1) {
      if (tid < s) {
        float vv = rv[tid+s]; int i2 = ri[tid+s];
        if (vv > rv[tid] || (vv == rv[tid] && i2 < ri[tid])) { rv[tid]=vv; ri[tid]=i2; }
      }
      __syncthreads();
    }
    if (tid == 0) { out[it] = ri[0]; sv[ri[0]] = -INFINITY; }
    __syncthreads();
  }
}

// ---------------- 4) gathers ----------------
__global__ void __launch_bounds__(256) gather_kernel(const float* __restrict__ q,
                                                     const float* __restrict__ k,
                                                     const float* __restrict__ v) {
  unsigned wi = (blockIdx.x * 256u + threadIdx.x) >> 5;
  int lane = threadIdx.x & 31;
  if (wi >= (unsigned)(BH_*S_)) return;
  int bh = wi / S_;
  int rr = wi % S_;
  int g = rr / MK_, tt = rr % MK_;
  int kj = g_kidx[(bh*G_+g)*MK_+tt];
  int qj = g_qidx[(bh*G_+g)*MK_+tt];
  size_t srck = ((size_t)bh*NTOK + g*P_ + kj) << 7;
  size_t srcq = ((size_t)bh*NTOK + g*P_ + qj) << 7;
  size_t dst  = ((size_t)wi << 7) + lane*4;
  *(float4*)(g_ksub    + dst) = *(const float4*)(k + srck + lane*4);
  *(float4*)(g_vsub    + dst) = *(const float4*)(v + srck + lane*4);
  *(float4*)(g_krepsub + dst) = *(const float4*)(g_krep + (((size_t)bh*P_ + kj) << 7) + lane*4);
  *(float4*)(g_qsub    + dst) = *(const float4*)(q + srcq + lane*4);
}

// ---------------- 5) tiled flash attention with FFMA2 ----------------
// modes: 0 p0, 1 p1-del, 2 p1-add, 3 p2
// grid: (qpad/BQ, ns, BH_), block 256, dynamic smem SMEM_BYTES.
// writes unnormalized partials (o, m, l) to g_part_*.
__global__ void __launch_bounds__(256, 1)
attn_tile_kernel(int mode, const float* __restrict__ kx, const float* __restrict__ vx) {
  const float *Q, *K, *V; int nq, nk, kps, qpad; size_t qstr, kstr;
  if (mode == 0)      { Q=g_qrep; K=g_krep;    V=g_vmean; nq=P_; nk=P_;   kps=P_;   qpad=P_;  qstr=(size_t)P_*D_; kstr=(size_t)P_*D_; }
  else if (mode == 1) { Q=g_qrep; K=g_krepsub; V=g_vsub;  nq=P_; nk=S_;   kps=S_;   qpad=P_;  qstr=(size_t)P_*D_; kstr=(size_t)S_*D_; }
  else if (mode == 2) { Q=g_qrep; K=g_ksub;    V=g_vsub;  nq=P_; nk=S_;   kps=S_;   qpad=P_;  qstr=(size_t)P_*D_; kstr=(size_t)S_*D_; }
  else                { Q=g_qsub; K=kx;        V=vx;      nq=S_; nk=NTOK; kps=1024; qpad=384; qstr=(size_t)S_*D_; kstr=(size_t)NTOK*D_; }

  extern __shared__ float sm[];
  float* Qs = sm;                       // [c][QSROW]
  float* Ks = Qs + 128*QSROW;           // [c][KSROW]
  float* Vs = Ks + 128*KSROW;           // [k][VSROW]
  float* Ps = Vs + 64*VSROW;            // [q][PSROW]

  int bh = blockIdx.z;
  Q += (size_t)bh*qstr; K += (size_t)bh*kstr; V += (size_t)bh*kstr;
  int q0  = blockIdx.x * BQ;
  int ks0 = blockIdx.y * kps;
  int ke  = ks0 + kps; if (ke > nk) ke = nk;

  int tid = threadIdx.x;
  int tq = tid >> 4, tk = tid & 15;

  // ---- load Q tile transposed (scaled), swizzled by dim ----
#pragma unroll
  for (int t = 0; t < 16; t++) {
    int idx = tid + t*256;              // 4096 float4
    int row = idx >> 5, c4 = idx & 31;
    int grow = q0 + row; if (grow > nq-1) grow = nq-1;
    float4 qv = *(const float4*)(Q + ((size_t)grow << 7) + c4*4);
    int f2s = (c4 & 7) * 8;
    int col = row ^ f2s;
    float* dst = Qs + (c4*4)*QSROW + col;
    dst[0]       = qv.x * SCALE_F;
    dst[QSROW]   = qv.y * SCALE_F;
    dst[2*QSROW] = qv.z * SCALE_F;
    dst[3*QSROW] = qv.w * SCALE_F;
  }

  F2 o2[8][4];
#pragma unroll
  for (int i = 0; i < 8; i++)
#pragma unroll
    for (int j = 0; j < 4; j++) o2[i][j].f = make_float2(0.f, 0.f);
  float m[8], l[8];
#pragma unroll
  for (int i = 0; i < 8; i++) { m[i] = -INFINITY; l[i] = 0.f; }

  int ntile = (ke - ks0 + BK - 1) / BK;
  for (int tile = 0; tile < ntile; tile++) {
    int kb = ks0 + tile*BK;
    __syncthreads();   // previous PV done before overwriting tiles
    // ---- load K transposed (swizzled) + V direct ----
#pragma unroll
    for (int t = 0; t < 8; t++) {
      int idx = tid + t*256;            // 2048 float4
      int kr = idx >> 5, c4 = idx & 31;
      int gk = kb + kr;
      float4 kv = make_float4(0,0,0,0), vv = kv;
      if (gk < ke) {
        kv = *(const float4*)(K + ((size_t)gk << 7) + c4*4);
        vv = *(const float4*)(V + ((size_t)gk << 7) + c4*4);
      }
      int col = kr ^ ((c4 & 7) * 4);
      float* dk = Ks + (c4*4)*KSROW + col;
      dk[0]       = kv.x;
      dk[KSROW]   = kv.y;
      dk[2*KSROW] = kv.z;
      dk[3*KSROW] = kv.w;
      *(float4*)(Vs + kr*VSROW + c4*4) = vv;
    }
    __syncthreads();

    // ---- S = Q K^T (8q x 4k per thread, f32x2 pairs over q) ----
    F2 acc[4][4];
#pragma unroll
    for (int a = 0; a < 4; a++)
#pragma unroll
      for (int b = 0; b < 4; b++) acc[a][b].f = make_float2(0.f, 0.f);

#pragma unroll 8
    for (int c = 0; c < 128; c++) {
      int f2s = ((c >> 2) & 7) * 8;
      int fks = ((c >> 2) & 7) * 4;
      const float* qrow = Qs + c*QSROW + ((8*tq) ^ f2s);
      float4 qa = *(const float4*)(qrow);
      float4 qb = *(const float4*)(qrow + 4);
      float4 kv = *(const float4*)(Ks + c*KSROW + ((4*tk) ^ fks));
      F2 qp0 = pk2(qa.x, qa.y), qp1 = pk2(qa.z, qa.w);
      F2 qp2 = pk2(qb.x, qb.y), qp3 = pk2(qb.z, qb.w);
      F2 k0 = dup2(kv.x), k1 = dup2(kv.y), k2 = dup2(kv.z), k3 = dup2(kv.w);
      fma2(acc[0][0], qp0, k0); fma2(acc[1][0], qp1, k0);
      fma2(acc[2][0], qp2, k0); fma2(acc[3][0], qp3, k0);
      fma2(acc[0][1], qp0, k1); fma2(acc[1][1], qp1, k1);
      fma2(acc[2][1], qp2, k1); fma2(acc[3][1], qp3, k1);
      fma2(acc[0][2], qp0, k2); fma2(acc[1][2], qp1, k2);
      fma2(acc[2][2], qp2, k2); fma2(acc[3][2], qp3, k2);
      fma2(acc[0][3], qp0, k3); fma2(acc[1][3], qp1, k3);
      fma2(acc[2][3], qp2, k3); fma2(acc[3][3], qp3, k3);
    }

    // ---- online softmax ----
    float s[8][4];
    int jb = kb + 4*tk;
#pragma unroll
    for (int iq = 0; iq < 4; iq++)
#pragma unroll
      for (int j = 0; j < 4; j++) {
        float vx0 = acc[iq][j].f.x, vx1 = acc[iq][j].f.y;
        if (jb + j >= ke) { vx0 = -INFINITY; vx1 = -INFINITY; }
        s[2*iq][j] = vx0; s[2*iq+1][j] = vx1;
      }
    float rmax[8];
#pragma unroll
    for (int i = 0; i < 8; i++) {
      float r0 = fmaxf(fmaxf(s[i][0], s[i][1]), fmaxf(s[i][2], s[i][3]));
#pragma unroll
      for (int off = 8; off; off >>= 1)
        r0 = fmaxf(r0, __shfl_xor_sync(0xffffffffu, r0, off));
      rmax[i] = r0;
    }
    float rsum[8];
#pragma unroll
    for (int i = 0; i < 8; i++) {
      float mnew = fmaxf(m[i], rmax[i]);
      float corr = __expf(m[i] - mnew);
      m[i] = mnew;
      l[i] *= corr;
      F2 cd = dup2(corr);
      mul2(o2[i][0], o2[i][0], cd);
      mul2(o2[i][1], o2[i][1], cd);
      mul2(o2[i][2], o2[i][2], cd);
      mul2(o2[i][3], o2[i][3], cd);
      float p0 = __expf(s[i][0] - mnew);
      float p1 = __expf(s[i][1] - mnew);
      float p2v = __expf(s[i][2] - mnew);
      float p3 = __expf(s[i][3] - mnew);
      rsum[i] = (p0 + p1) + (p2v + p3);
      *(float4*)(Ps + (8*tq + i)*PSROW + 4*tk) = make_float4(p0, p1, p2v, p3);
    }
#pragma unroll
    for (int i = 0; i < 8; i++) {
      float r0 = rsum[i];
#pragma unroll
      for (int off = 8; off; off >>= 1)
        r0 += __shfl_xor_sync(0xffffffffu, r0, off);
      l[i] += r0;
    }
    __syncthreads();

    // ---- O += P V (8q x 8d per thread, pairs over d) ----
#pragma unroll 2
    for (int k4 = 0; k4 < 16; k4++) {
      float pv[8][4];
#pragma unroll
      for (int i = 0; i < 8; i++) {
        float4 p4 = *(const float4*)(Ps + (8*tq + i)*PSROW + 4*k4);
        pv[i][0] = p4.x; pv[i][1] = p4.y; pv[i][2] = p4.z; pv[i][3] = p4.w;
      }
#pragma unroll
      for (int kk = 0; kk < 4; kk++) {
        int k = 4*k4 + kk;
        float4 va = *(const float4*)(Vs + k*VSROW + 4*tk);
        float4 vb = *(const float4*)(Vs + k*VSROW + 64 + 4*tk);
        F2 v0 = pk2(va.x, va.y), v1 = pk2(va.z, va.w);
        F2 v2 = pk2(vb.x, vb.y), v3 = pk2(vb.z, vb.w);
#pragma unroll
        for (int i = 0; i < 8; i++) {
          F2 pd = dup2(pv[i][kk]);
          fma2(o2[i][0], pd, v0);
          fma2(o2[i][1], pd, v1);
          fma2(o2[i][2], pd, v2);
          fma2(o2[i][3], pd, v3);
        }
      }
    }
  }

  // ---- store partials (unnormalized) ----
  size_t pb = ((size_t)(blockIdx.y*BH_ + bh)*qpad + q0);
#pragma unroll
  for (int i = 0; i < 8; i++) {
    int row = 8*tq + i;
    float4 w0 = make_float4(o2[i][0].f.x, o2[i][0].f.y, o2[i][1].f.x, o2[i][1].f.y);
    float4 w1 = make_float4(o2[i][2].f.x, o2[i][2].f.y, o2[i][3].f.x, o2[i][3].f.y);
    float* dst = g_part_o + ((pb + row) << 7);
    *(float4*)(dst + 4*tk)      = w0;
    *(float4*)(dst + 64 + 4*tk) = w1;
    if (tk == 0) { g_part_m[pb + row] = m[i]; g_part_l[pb + row] = l[i]; }
  }
}

// ---------------- 5b) split-K merge / normalize ----------------
__global__ void __launch_bounds__(256) merge_kernel(int mode) {
  float *dest_o, *dest_l; int nq, qpad, ns;
  if (mode == 0)      { dest_o=g_attn1; dest_l=g_lse1; nq=P_; qpad=P_;  ns=1; }
  else if (mode == 1) { dest_o=g_adel;  dest_l=g_ldel; nq=P_; qpad=P_;  ns=1; }
  else if (mode == 2) { dest_o=g_aadd;  dest_l=g_ladd; nq=P_; qpad=P_;  ns=1; }
  else                { dest_o=g_a2;    dest_l=g_l2;   nq=S_; qpad=384; ns=8; }
  int bh = blockIdx.y;
  int w = threadIdx.x >> 5, lane = threadIdx.x & 31;
  int row = blockIdx.x*8 + w;
  if (row >= nq) return;
  float M = -INFINITY;
#pragma unroll 8
  for (int s = 0; s < ns; s++)
    M = fmaxf(M, g_part_m[(size_t)(s*BH_ + bh)*qpad + row]);
  float L = 0.f;
  float4 o = make_float4(0,0,0,0);
#pragma unroll 8
  for (int s = 0; s < ns; s++) {
    size_t ri = (size_t)(s*BH_ + bh)*qpad + row;
    float wgt = __expf(g_part_m[ri] - M);
    L += g_part_l[ri] * wgt;
    float4 po = *(const float4*)(g_part_o + (ri << 7) + lane*4);
    o.x += po.x*wgt; o.y += po.y*wgt; o.z += po.z*wgt; o.w += po.w*wgt;
  }
  float inv = 1.0f / L;
  o.x*=inv; o.y*=inv; o.z*=inv; o.w*=inv;
  *(float4*)(dest_o + (((size_t)bh*nq + row) << 7) + lane*4) = o;
  if (lane == 0) dest_l[(size_t)bh*nq + row] = M + logf(L);
}

// ---------------- 6) p1 combine + broadcast write ----------------
__global__ void __launch_bounds__(256) combine_kernel(float* __restrict__ out, int has_lse) {
  unsigned wi = (blockIdx.x * 256u + threadIdx.x) >> 5;
  int lane = threadIdx.x & 31;
  int bh = wi >> 10, j = wi & 1023;
  float l1 = g_lse1[wi] + LN8_F;
  float ld = g_ldel[wi];
  float la = g_ladd[wi];
  float c1 = expf(ld - l1);
  float inv1 = 1.0f / (1.0f - c1);
  float lp1 = l1 + log1pf(-c1);
  float c2 = 1.0f / (1.0f + expf(la - lp1));
  float lse = fmaxf(lp1, la) + log1pf(expf(-fabsf(lp1 - la)));
  size_t off = ((size_t)wi << 7) + lane*4;
  float4 a0 = *(const float4*)(g_attn1 + off);
  float4 ad = *(const float4*)(g_adel + off);
  float4 aa = *(const float4*)(g_aadd + off);
  float4 r;
  float c2b = 1.0f - c2;
  r.x = c2*((a0.x - c1*ad.x)*inv1) + c2b*aa.x;
  r.y = c2*((a0.y - c1*ad.y)*inv1) + c2b*aa.y;
  r.z = c2*((a0.z - c1*ad.z)*inv1) + c2b*aa.z;
  r.w = c2*((a0.w - c1*ad.w)*inv1) + c2b*aa.w;
  float* outl = out + (size_t)BH_*NTOK*D_;
#pragma unroll
  for (int g = 0; g < G_; g++) {
    size_t orow = (size_t)bh*NTOK + g*P_ + j;
    *(float4*)(out + (orow << 7) + lane*4) = r;
    if (lane == 0 && has_lse) outl[orow] = lse;
  }
}

// ---------------- 7) p2 scatter ----------------
__global__ void __launch_bounds__(256) scatter_kernel(float* __restrict__ out, int has_lse) {
  unsigned wi = (blockIdx.x * 256u + threadIdx.x) >> 5;
  int lane = threadIdx.x & 31;
  if (wi >= (unsigned)(BH_*S_)) return;
  int bh = wi / S_;
  int rr = wi % S_;
  int g = rr / MK_, tt = rr % MK_;
  int qj = g_qidx[(bh*G_+g)*MK_+tt];
  size_t orow = (size_t)bh*NTOK + g*P_ + qj;
  float4 a = *(const float4*)(g_a2 + ((size_t)wi << 7) + lane*4);
  *(float4*)(out + (orow << 7) + lane*4) = a;
  if (lane == 0 && has_lse) out[(size_t)BH_*NTOK*D_ + orow] = g_l2[wi];
}

// ---------------- launch ----------------
extern "C" void kernel_launch(void* const* d_in, const int* in_sizes, int n_in,
                              void* d_out, int out_size) {
  const float* q = (const float*)d_in[0];
  const float* k = (const float*)d_in[1];
  const float* v = (const float*)d_in[2];
  float* out = (float*)d_out;
  int has_lse = (out_size >= BH_*NTOK*(D_ + 1)) ? 1 : 0;

  cudaFuncSetAttribute(attn_tile_kernel,
                       cudaFuncAttributeMaxDynamicSharedMemorySize, SMEM_BYTES);

  means_kernel <<<(BH_*P_*32)/256, 256>>>(q, k, v);
  scores_kernel<<<(2*BH_*G_*P_*32)/256, 256>>>(q, k);
  topk_kernel  <<<dim3(BH_*G_, 2), 256>>>();
  gather_kernel<<<(BH_*S_*32 + 255)/256, 256>>>(q, k, v);

  attn_tile_kernel<<<dim3(P_/BQ, 1, BH_), 256, SMEM_BYTES>>>(0, nullptr, nullptr);
  merge_kernel    <<<dim3(P_/8, BH_), 256>>>(0);
  attn_tile_kernel<<<dim3(P_/BQ, 1, BH_), 256, SMEM_BYTES>>>(1, nullptr, nullptr);
  merge_kernel    <<<dim3(P_/8, BH_), 256>>>(1);
  attn_tile_kernel<<<dim3(P_/BQ, 1, BH_), 256, SMEM_BYTES>>>(2, nullptr, nullptr);
  merge_kernel    <<<dim3(P_/8, BH_), 256>>>(2);
  attn_tile_kernel<<<dim3(384/BQ, 8, BH_), 256, SMEM_BYTES>>>(3, k, v);
  merge_kernel    <<<dim3((S_+7)/8, BH_), 256>>>(3);

  combine_kernel<<<(BH_*P_*32)/256, 256>>>(out, has_lse);
  scatter_kernel<<<(BH_*S_*32 + 255)/256, 256>>>(out, has_lse);
}

// round 5
// speedup vs baseline: 2.6613x; 1.0006x over previous
#include <cuda_runtime.h>
#include <stdint.h>
#include <math.h>

// ---------------- problem constants (fixed shapes) ----------------
#define B_    2
#define H_    16
#define NTOK  8192
#define D_    128
#define G_    8
#define P_    1024
#define MK_   34
#define S_    (G_*MK_)        // 272
#define BH_   (B_*H_)         // 32

#define SCALE_F 0.08838834764831843f   // 128^-0.5
#define LN8_F   2.0794415416798357f
#define TINY_F  1.17549435e-38f
#define EPS_F   1.1920929e-07f

// attention tiling
#define BQ 128
#define BK 64
#define QSROW 132      // Qs: [128 dims][132] (holds 128 q rows + pad)
#define KSROW 68       // Ks: [128 dims][68]  (holds 64 k + pad)
#define VSROW 132      // Vs: [64 k][132]     (holds 128 d + pad)
#define PSROW 68       // Ps: [128 q][68]     (holds 64 k + pad)
#define SMEM_FLOATS (128*QSROW + 128*KSROW + 64*VSROW + 128*PSROW)
#define SMEM_BYTES  (SMEM_FLOATS*4)

// ---------------- scratch (device globals; no allocations) ----------------
__device__ __align__(16) float g_qrep [BH_*P_*D_];
__device__ __align__(16) float g_krep [BH_*P_*D_];
__device__ __align__(16) float g_vmean[BH_*P_*D_];
__device__ __align__(16) float g_attn1[BH_*P_*D_];
__device__ __align__(16) float g_adel [BH_*P_*D_];
__device__ __align__(16) float g_aadd [BH_*P_*D_];
__device__ float g_lse1[BH_*P_];
__device__ float g_ldel[BH_*P_];
__device__ float g_ladd[BH_*P_];
__device__ float g_score_k[BH_*G_*P_];
__device__ float g_score_q[BH_*G_*P_];
__device__ int   g_kidx[BH_*G_*MK_];
__device__ int   g_qidx[BH_*G_*MK_];
__device__ __align__(16) float g_ksub   [BH_*S_*D_];
__device__ __align__(16) float g_krepsub[BH_*S_*D_];
__device__ __align__(16) float g_vsub   [BH_*S_*D_];
__device__ __align__(16) float g_qsub   [BH_*S_*D_];
__device__ __align__(16) float g_a2     [BH_*S_*D_];
__device__ float g_l2[BH_*S_];
// split-K partials: max ns*BH*qpad = 8*32*384 rows
__device__ __align__(16) float g_part_o[8*BH_*384*D_];
__device__ float g_part_m[8*BH_*384 + 1024];
__device__ float g_part_l[8*BH_*384 + 1024];

// ---------------- f32x2 packed math ----------------
typedef unsigned long long ull_t;
union F2 { float2 f; ull_t u; };
__device__ __forceinline__ void fma2(F2& d, F2 a, F2 b) {
  asm("fma.rn.f32x2 %0, %1, %2, %0;" : "+l"(d.u) : "l"(a.u), "l"(b.u));
}
__device__ __forceinline__ void mul2(F2& d, F2 a, F2 b) {
  asm("mul.rn.f32x2 %0, %1, %2;" : "=l"(d.u) : "l"(a.u), "l"(b.u));
}
__device__ __forceinline__ F2 dup2(float x) { F2 r; r.f = make_float2(x, x); return r; }
__device__ __forceinline__ F2 pk2(float x, float y) { F2 r; r.f = make_float2(x, y); return r; }

// ---------------- JAX threefry2x32 (20 rounds) ----------------
__device__ __forceinline__ void threefry2x32(uint32_t k0, uint32_t k1,
                                             uint32_t x0, uint32_t x1,
                                             uint32_t& o0, uint32_t& o1) {
  uint32_t k2 = k0 ^ k1 ^ 0x1BD11BDAu;
  x0 += k0; x1 += k1;
#define TFR(r) { x0 += x1; x1 = (x1 << (r)) | (x1 >> (32 - (r))); x1 ^= x0; }
  TFR(13) TFR(15) TFR(26) TFR(6)   x0 += k1; x1 += k2 + 1u;
  TFR(17) TFR(29) TFR(16) TFR(24)  x0 += k2; x1 += k0 + 2u;
  TFR(13) TFR(15) TFR(26) TFR(6)   x0 += k0; x1 += k1 + 3u;
  TFR(17) TFR(29) TFR(16) TFR(24)  x0 += k1; x1 += k2 + 4u;
  TFR(13) TFR(15) TFR(26) TFR(6)   x0 += k2; x1 += k0 + 5u;
#undef TFR
  o0 = x0; o1 = x1;
}

// ---------------- 1) group means ----------------
__global__ void __launch_bounds__(256) means_kernel(const float* __restrict__ q,
                                                    const float* __restrict__ k,
                                                    const float* __restrict__ v) {
  int idx = blockIdx.x * 256 + threadIdx.x;          // over BH_*P_*32 float4
  int bh  = idx / (P_*32);
  int rem = idx - bh * (P_*32);
  const float4* q4 = (const float4*)q + (size_t)bh*NTOK*32 + rem;
  const float4* k4 = (const float4*)k + (size_t)bh*NTOK*32 + rem;
  const float4* v4 = (const float4*)v + (size_t)bh*NTOK*32 + rem;
  float4 sq = make_float4(0,0,0,0), sk = sq, sv = sq;
#pragma unroll
  for (int g = 0; g < G_; g++) {
    float4 a = q4[(size_t)g*P_*32]; sq.x+=a.x; sq.y+=a.y; sq.z+=a.z; sq.w+=a.w;
    float4 b = k4[(size_t)g*P_*32]; sk.x+=b.x; sk.y+=b.y; sk.z+=b.z; sk.w+=b.w;
    float4 c = v4[(size_t)g*P_*32]; sv.x+=c.x; sv.y+=c.y; sv.z+=c.z; sv.w+=c.w;
  }
  const float s = 1.0f / G_;
  sq.x*=s; sq.y*=s; sq.z*=s; sq.w*=s;
  sk.x*=s; sk.y*=s; sk.z*=s; sk.w*=s;
  sv.x*=s; sv.y*=s; sv.z*=s; sv.w*=s;
  ((float4*)g_qrep )[idx] = sq;
  ((float4*)g_krep )[idx] = sk;
  ((float4*)g_vmean)[idx] = sv;
}

// ---------------- 2) residual-norm + gumbel scores ----------------
__global__ void __launch_bounds__(256) scores_kernel(const float* __restrict__ q,
                                                     const float* __restrict__ k) {
  unsigned wi = (blockIdx.x * 256u + threadIdx.x) >> 5;
  int lane = threadIdx.x & 31;
  const unsigned RT = (unsigned)(BH_*G_*P_);
  int t = wi >= RT;
  unsigned r  = t ? wi - RT : wi;
  unsigned bh = r >> 13;
  unsigned g  = (r >> 10) & 7u;
  unsigned j  = r & 1023u;
  const float* x  = (t ? q : k)           + (((size_t)bh*NTOK + g*P_ + j) << 7);
  const float* rp = (t ? g_qrep : g_krep) + (((size_t)bh*P_ + j) << 7);
  float4 a = *(const float4*)(x  + lane*4);
  float4 b = *(const float4*)(rp + lane*4);
  float dx=a.x-b.x, dy=a.y-b.y, dz=a.z-b.z, dw=a.w-b.w;
  float ss = dx*dx + dy*dy + dz*dz + dw*dw;
#pragma unroll
  for (int off = 16; off; off >>= 1)
    ss += __shfl_xor_sync(0xffffffffu, ss, off);
  if (lane == 0) {
    uint32_t rk0, rk1, o0, o1;
    threefry2x32(0u, 42u, 0u, (uint32_t)t, rk0, rk1);
    threefry2x32(rk0, rk1, 0u, r, o0, o1);
    uint32_t bits = o0 ^ o1;
    float u = __uint_as_float((bits >> 9) | 0x3f800000u) - 1.0f;
    if (u <= 0.0f) u = TINY_F;
    float gum = -logf(-logf(u));
    float score = logf(sqrtf(ss) * 100.0f + EPS_F) + gum;
    (t ? g_score_q : g_score_k)[r] = score;
  }
}

// ---------------- 3) top-34 per group of 1024 ----------------
__global__ void __launch_bounds__(256) topk_kernel() {
  int grp = blockIdx.x;
  int t   = blockIdx.y;
  float* sc = (t ? g_score_q : g_score_k) + (size_t)grp * P_;
  int*  out = (t ? g_qidx    : g_kidx   ) + (size_t)grp * MK_;
  __shared__ float sv[1024];
  __shared__ float rv[256];
  __shared__ int   ri[256];
  int tid = threadIdx.x;
#pragma unroll
  for (int r = 0; r < 4; r++) sv[tid + 256*r] = sc[tid + 256*r];
  __syncthreads();
  for (int it = 0; it < MK_; it++) {
    float bv = -INFINITY; int bi = 0x7fffffff;
#pragma unroll
    for (int r = 0; r < 4; r++) {
      int i = tid + 256*r;
      float vv = sv[i];
      if (vv > bv || (vv == bv && i < bi)) { bv = vv; bi = i; }
    }
    rv[tid] = bv; ri[tid] = bi;
    __syncthreads();
    for (int s = 128; s; s >>= 1) {
      if (tid < s) {
        float vv = rv[tid+s]; int i2 = ri[tid+s];
        if (vv > rv[tid] || (vv == rv[tid] && i2 < ri[tid])) { rv[tid]=vv; ri[tid]=i2; }
      }
      __syncthreads();
    }
    if (tid == 0) { out[it] = ri[0]; sv[ri[0]] = -INFINITY; }
    __syncthreads();
  }
}

// ---------------- 4) gathers ----------------
__global__ void __launch_bounds__(256) gather_kernel(const float* __restrict__ q,
                                                     const float* __restrict__ k,
                                                     const float* __restrict__ v) {
  unsigned wi = (blockIdx.x * 256u + threadIdx.x) >> 5;
  int lane = threadIdx.x & 31;
  if (wi >= (unsigned)(BH_*S_)) return;
  int bh = wi / S_;
  int rr = wi % S_;
  int g = rr / MK_, tt = rr % MK_;
  int kj = g_kidx[(bh*G_+g)*MK_+tt];
  int qj = g_qidx[(bh*G_+g)*MK_+tt];
  size_t srck = ((size_t)bh*NTOK + g*P_ + kj) << 7;
  size_t srcq = ((size_t)bh*NTOK + g*P_ + qj) << 7;
  size_t dst  = ((size_t)wi << 7) + lane*4;
  *(float4*)(g_ksub    + dst) = *(const float4*)(k + srck + lane*4);
  *(float4*)(g_vsub    + dst) = *(const float4*)(v + srck + lane*4);
  *(float4*)(g_krepsub + dst) = *(const float4*)(g_krep + (((size_t)bh*P_ + kj) << 7) + lane*4);
  *(float4*)(g_qsub    + dst) = *(const float4*)(q + srcq + lane*4);
}

// ---------------- 5) tiled flash attention with FFMA2 ----------------
// modes: 0 p0, 1 p1-del, 2 p1-add, 3 p2
// grid: (qpad/BQ, ns, BH_), block 256, dynamic smem SMEM_BYTES.
// writes unnormalized partials (o, m, l) to g_part_*.
__global__ void __launch_bounds__(256, 1)
attn_tile_kernel(int mode, const float* __restrict__ kx, const float* __restrict__ vx) {
  const float *Q, *K, *V; int nq, nk, kps, qpad; size_t qstr, kstr;
  if (mode == 0)      { Q=g_qrep; K=g_krep;    V=g_vmean; nq=P_; nk=P_;   kps=P_;   qpad=P_;  qstr=(size_t)P_*D_; kstr=(size_t)P_*D_; }
  else if (mode == 1) { Q=g_qrep; K=g_krepsub; V=g_vsub;  nq=P_; nk=S_;   kps=S_;   qpad=P_;  qstr=(size_t)P_*D_; kstr=(size_t)S_*D_; }
  else if (mode == 2) { Q=g_qrep; K=g_ksub;    V=g_vsub;  nq=P_; nk=S_;   kps=S_;   qpad=P_;  qstr=(size_t)P_*D_; kstr=(size_t)S_*D_; }
  else                { Q=g_qsub; K=kx;        V=vx;      nq=S_; nk=NTOK; kps=1024; qpad=384; qstr=(size_t)S_*D_; kstr=(size_t)NTOK*D_; }

  extern __shared__ float sm[];
  float* Qs = sm;                       // [c][QSROW]
  float* Ks = Qs + 128*QSROW;           // [c][KSROW]
  float* Vs = Ks + 128*KSROW;           // [k][VSROW]
  float* Ps = Vs + 64*VSROW;            // [q][PSROW]

  int bh = blockIdx.z;
  Q += (size_t)bh*qstr; K += (size_t)bh*kstr; V += (size_t)bh*kstr;
  int q0  = blockIdx.x * BQ;
  int ks0 = blockIdx.y * kps;
  int ke  = ks0 + kps; if (ke > nk) ke = nk;

  int tid = threadIdx.x;
  int tq = tid >> 4, tk = tid & 15;

  // ---- load Q tile transposed (scaled), swizzled by dim ----
#pragma unroll
  for (int t = 0; t < 16; t++) {
    int idx = tid + t*256;              // 4096 float4
    int row = idx >> 5, c4 = idx & 31;
    int grow = q0 + row; if (grow > nq-1) grow = nq-1;
    float4 qv = *(const float4*)(Q + ((size_t)grow << 7) + c4*4);
    int f2s = (c4 & 7) * 8;
    int col = row ^ f2s;
    float* dst = Qs + (c4*4)*QSROW + col;
    dst[0]       = qv.x * SCALE_F;
    dst[QSROW]   = qv.y * SCALE_F;
    dst[2*QSROW] = qv.z * SCALE_F;
    dst[3*QSROW] = qv.w * SCALE_F;
  }

  F2 o2[8][4];
#pragma unroll
  for (int i = 0; i < 8; i++)
#pragma unroll
    for (int j = 0; j < 4; j++) o2[i][j].f = make_float2(0.f, 0.f);
  float m[8], l[8];
#pragma unroll
  for (int i = 0; i < 8; i++) { m[i] = -INFINITY; l[i] = 0.f; }

  int ntile = (ke - ks0 + BK - 1) / BK;
  for (int tile = 0; tile < ntile; tile++) {
    int kb = ks0 + tile*BK;
    __syncthreads();   // previous PV done before overwriting tiles
    // ---- load K transposed (swizzled) + V direct ----
#pragma unroll
    for (int t = 0; t < 8; t++) {
      int idx = tid + t*256;            // 2048 float4
      int kr = idx >> 5, c4 = idx & 31;
      int gk = kb + kr;
      float4 kv = make_float4(0,0,0,0), vv = kv;
      if (gk < ke) {
        kv = *(const float4*)(K + ((size_t)gk << 7) + c4*4);
        vv = *(const float4*)(V + ((size_t)gk << 7) + c4*4);
      }
      int col = kr ^ ((c4 & 7) * 4);
      float* dk = Ks + (c4*4)*KSROW + col;
      dk[0]       = kv.x;
      dk[KSROW]   = kv.y;
      dk[2*KSROW] = kv.z;
      dk[3*KSROW] = kv.w;
      *(float4*)(Vs + kr*VSROW + c4*4) = vv;
    }
    __syncthreads();

    // ---- S = Q K^T (8q x 4k per thread, f32x2 pairs over q) ----
    F2 acc[4][4];
#pragma unroll
    for (int a = 0; a < 4; a++)
#pragma unroll
      for (int b = 0; b < 4; b++) acc[a][b].f = make_float2(0.f, 0.f);

#pragma unroll 8
    for (int c = 0; c < 128; c++) {
      int f2s = ((c >> 2) & 7) * 8;
      int fks = ((c >> 2) & 7) * 4;
      const float* qrow = Qs + c*QSROW + ((8*tq) ^ f2s);
      float4 qa = *(const float4*)(qrow);
      float4 qb = *(const float4*)(qrow + 4);
      float4 kv = *(const float4*)(Ks + c*KSROW + ((4*tk) ^ fks));
      F2 qp0 = pk2(qa.x, qa.y), qp1 = pk2(qa.z, qa.w);
      F2 qp2 = pk2(qb.x, qb.y), qp3 = pk2(qb.z, qb.w);
      F2 k0 = dup2(kv.x), k1 = dup2(kv.y), k2 = dup2(kv.z), k3 = dup2(kv.w);
      fma2(acc[0][0], qp0, k0); fma2(acc[1][0], qp1, k0);
      fma2(acc[2][0], qp2, k0); fma2(acc[3][0], qp3, k0);
      fma2(acc[0][1], qp0, k1); fma2(acc[1][1], qp1, k1);
      fma2(acc[2][1], qp2, k1); fma2(acc[3][1], qp3, k1);
      fma2(acc[0][2], qp0, k2); fma2(acc[1][2], qp1, k2);
      fma2(acc[2][2], qp2, k2); fma2(acc[3][2], qp3, k2);
      fma2(acc[0][3], qp0, k3); fma2(acc[1][3], qp1, k3);
      fma2(acc[2][3], qp2, k3); fma2(acc[3][3], qp3, k3);
    }

    // ---- online softmax ----
    float s[8][4];
    int jb = kb + 4*tk;
#pragma unroll
    for (int iq = 0; iq < 4; iq++)
#pragma unroll
      for (int j = 0; j < 4; j++) {
        float vx0 = acc[iq][j].f.x, vx1 = acc[iq][j].f.y;
        if (jb + j >= ke) { vx0 = -INFINITY; vx1 = -INFINITY; }
        s[2*iq][j] = vx0; s[2*iq+1][j] = vx1;
      }
    float rmax[8];
#pragma unroll
    for (int i = 0; i < 8; i++) {
      float r0 = fmaxf(fmaxf(s[i][0], s[i][1]), fmaxf(s[i][2], s[i][3]));
#pragma unroll
      for (int off = 8; off; off >>= 1)
        r0 = fmaxf(r0, __shfl_xor_sync(0xffffffffu, r0, off));
      rmax[i] = r0;
    }
    float rsum[8];
#pragma unroll
    for (int i = 0; i < 8; i++) {
      float mnew = fmaxf(m[i], rmax[i]);
      float corr = __expf(m[i] - mnew);
      m[i] = mnew;
      l[i] *= corr;
      F2 cd = dup2(corr);
      mul2(o2[i][0], o2[i][0], cd);
      mul2(o2[i][1], o2[i][1], cd);
      mul2(o2[i][2], o2[i][2], cd);
      mul2(o2[i][3], o2[i][3], cd);
      float p0 = __expf(s[i][0] - mnew);
      float p1 = __expf(s[i][1] - mnew);
      float p2v = __expf(s[i][2] - mnew);
      float p3 = __expf(s[i][3] - mnew);
      rsum[i] = (p0 + p1) + (p2v + p3);
      *(float4*)(Ps + (8*tq + i)*PSROW + 4*tk) = make_float4(p0, p1, p2v, p3);
    }
#pragma unroll
    for (int i = 0; i < 8; i++) {
      float r0 = rsum[i];
#pragma unroll
      for (int off = 8; off; off >>= 1)
        r0 += __shfl_xor_sync(0xffffffffu, r0, off);
      l[i] += r0;
    }
    __syncthreads();

    // ---- O += P V (8q x 8d per thread, pairs over d) ----
#pragma unroll 2
    for (int k4 = 0; k4 < 16; k4++) {
      float pv[8][4];
#pragma unroll
      for (int i = 0; i < 8; i++) {
        float4 p4 = *(const float4*)(Ps + (8*tq + i)*PSROW + 4*k4);
        pv[i][0] = p4.x; pv[i][1] = p4.y; pv[i][2] = p4.z; pv[i][3] = p4.w;
      }
#pragma unroll
      for (int kk = 0; kk < 4; kk++) {
        int k = 4*k4 + kk;
        float4 va = *(const float4*)(Vs + k*VSROW + 4*tk);
        float4 vb = *(const float4*)(Vs + k*VSROW + 64 + 4*tk);
        F2 v0 = pk2(va.x, va.y), v1 = pk2(va.z, va.w);
        F2 v2 = pk2(vb.x, vb.y), v3 = pk2(vb.z, vb.w);
#pragma unroll
        for (int i = 0; i < 8; i++) {
          F2 pd = dup2(pv[i][kk]);
          fma2(o2[i][0], pd, v0);
          fma2(o2[i][1], pd, v1);
          fma2(o2[i][2], pd, v2);
          fma2(o2[i][3], pd, v3);
        }
      }
    }
  }

  // ---- store partials (unnormalized) ----
  size_t pb = ((size_t)(blockIdx.y*BH_ + bh)*qpad + q0);
#pragma unroll
  for (int i = 0; i < 8; i++) {
    int row = 8*tq + i;
    float4 w0 = make_float4(o2[i][0].f.x, o2[i][0].f.y, o2[i][1].f.x, o2[i][1].f.y);
    float4 w1 = make_float4(o2[i][2].f.x, o2[i][2].f.y, o2[i][3].f.x, o2[i][3].f.y);
    float* dst = g_part_o + ((pb + row) << 7);
    *(float4*)(dst + 4*tk)      = w0;
    *(float4*)(dst + 64 + 4*tk) = w1;
    if (tk == 0) { g_part_m[pb + row] = m[i]; g_part_l[pb + row] = l[i]; }
  }
}

// ---------------- 5b) split-K merge / normalize ----------------
__global__ void __launch_bounds__(256) merge_kernel(int mode) {
  float *dest_o, *dest_l; int nq, qpad, ns;
  if (mode == 0)      { dest_o=g_attn1; dest_l=g_lse1; nq=P_; qpad=P_;  ns=1; }
  else if (mode == 1) { dest_o=g_adel;  dest_l=g_ldel; nq=P_; qpad=P_;  ns=1; }
  else if (mode == 2) { dest_o=g_aadd;  dest_l=g_ladd; nq=P_; qpad=P_;  ns=1; }
  else                { dest_o=g_a2;    dest_l=g_l2;   nq=S_; qpad=384; ns=8; }
  int bh = blockIdx.y;
  int w = threadIdx.x >> 5, lane = threadIdx.x & 31;
  int row = blockIdx.x*8 + w;
  if (row >= nq) return;
  float M = -INFINITY;
#pragma unroll 8
  for (int s = 0; s < ns; s++)
    M = fmaxf(M, g_part_m[(size_t)(s*BH_ + bh)*qpad + row]);
  float L = 0.f;
  float4 o = make_float4(0,0,0,0);
#pragma unroll 8
  for (int s = 0; s < ns; s++) {
    size_t ri = (size_t)(s*BH_ + bh)*qpad + row;
    float wgt = __expf(g_part_m[ri] - M);
    L += g_part_l[ri] * wgt;
    float4 po = *(const float4*)(g_part_o + (ri << 7) + lane*4);
    o.x += po.x*wgt; o.y += po.y*wgt; o.z += po.z*wgt; o.w += po.w*wgt;
  }
  float inv = 1.0f / L;
  o.x*=inv; o.y*=inv; o.z*=inv; o.w*=inv;
  *(float4*)(dest_o + (((size_t)bh*nq + row) << 7) + lane*4) = o;
  if (lane == 0) dest_l[(size_t)bh*nq + row] = M + logf(L);
}

// ---------------- 6) p1 combine + broadcast write ----------------
__global__ void __launch_bounds__(256) combine_kernel(float* __restrict__ out, int has_lse) {
  unsigned wi = (blockIdx.x * 256u + threadIdx.x) >> 5;
  int lane = threadIdx.x & 31;
  int bh = wi >> 10, j = wi & 1023;
  float l1 = g_lse1[wi] + LN8_F;
  float ld = g_ldel[wi];
  float la = g_ladd[wi];
  float c1 = expf(ld - l1);
  float inv1 = 1.0f / (1.0f - c1);
  float lp1 = l1 + log1pf(-c1);
  float c2 = 1.0f / (1.0f + expf(la - lp1));
  float lse = fmaxf(lp1, la) + log1pf(expf(-fabsf(lp1 - la)));
  size_t off = ((size_t)wi << 7) + lane*4;
  float4 a0 = *(const float4*)(g_attn1 + off);
  float4 ad = *(const float4*)(g_adel + off);
  float4 aa = *(const float4*)(g_aadd + off);
  float4 r;
  float c2b = 1.0f - c2;
  r.x = c2*((a0.x - c1*ad.x)*inv1) + c2b*aa.x;
  r.y = c2*((a0.y - c1*ad.y)*inv1) + c2b*aa.y;
  r.z = c2*((a0.z - c1*ad.z)*inv1) + c2b*aa.z;
  r.w = c2*((a0.w - c1*ad.w)*inv1) + c2b*aa.w;
  float* outl = out + (size_t)BH_*NTOK*D_;
#pragma unroll
  for (int g = 0; g < G_; g++) {
    size_t orow = (size_t)bh*NTOK + g*P_ + j;
    *(float4*)(out + (orow << 7) + lane*4) = r;
    if (lane == 0 && has_lse) outl[orow] = lse;
  }
}

// ---------------- 7) p2 scatter ----------------
__global__ void __launch_bounds__(256) scatter_kernel(float* __restrict__ out, int has_lse) {
  unsigned wi = (blockIdx.x * 256u + threadIdx.x) >> 5;
  int lane = threadIdx.x & 31;
  if (wi >= (unsigned)(BH_*S_)) return;
  int bh = wi / S_;
  int rr = wi % S_;
  int g = rr / MK_, tt = rr % MK_;
  int qj = g_qidx[(bh*G_+g)*MK_+tt];
  size_t orow = (size_t)bh*NTOK + g*P_ + qj;
  float4 a = *(const float4*)(g_a2 + ((size_t)wi << 7) + lane*4);
  *(float4*)(out + (orow << 7) + lane*4) = a;
  if (lane == 0 && has_lse) out[(size_t)BH_*NTOK*D_ + orow] = g_l2[wi];
}

// ---------------- launch ----------------
extern "C" void kernel_launch(void* const* d_in, const int* in_sizes, int n_in,
                              void* d_out, int out_size) {
  const float* q = (const float*)d_in[0];
  const float* k = (const float*)d_in[1];
  const float* v = (const float*)d_in[2];
  float* out = (float*)d_out;
  int has_lse = (out_size >= BH_*NTOK*(D_ + 1)) ? 1 : 0;

  cudaFuncSetAttribute(attn_tile_kernel,
                       cudaFuncAttributeMaxDynamicSharedMemorySize, SMEM_BYTES);

  means_kernel <<<(BH_*P_*32)/256, 256>>>(q, k, v);
  scores_kernel<<<(2*BH_*G_*P_*32)/256, 256>>>(q, k);
  topk_kernel  <<<dim3(BH_*G_, 2), 256>>>();
  gather_kernel<<<(BH_*S_*32 + 255)/256, 256>>>(q, k, v);

  attn_tile_kernel<<<dim3(P_/BQ, 1, BH_), 256, SMEM_BYTES>>>(0, nullptr, nullptr);
  merge_kernel    <<<dim3(P_/8, BH_), 256>>>(0);
  attn_tile_kernel<<<dim3(P_/BQ, 1, BH_), 256, SMEM_BYTES>>>(1, nullptr, nullptr);
  merge_kernel    <<<dim3(P_/8, BH_), 256>>>(1);
  attn_tile_kernel<<<dim3(P_/BQ, 1, BH_), 256, SMEM_BYTES>>>(2, nullptr, nullptr);
  merge_kernel    <<<dim3(P_/8, BH_), 256>>>(2);
  attn_tile_kernel<<<dim3(384/BQ, 8, BH_), 256, SMEM_BYTES>>>(3, k, v);
  merge_kernel    <<<dim3((S_+7)/8, BH_), 256>>>(3);

  combine_kernel<<<(BH_*P_*32)/256, 256>>>(out, has_lse);
  scatter_kernel<<<(BH_*S_*32 + 255)/256, 256>>>(out, has_lse);
}

// round 8
// speedup vs baseline: 3.6346x; 1.3657x over previous
#include <cuda_runtime.h>
#include <stdint.h>
#include <math.h>

#define B_    2
#define H_    16
#define NTOK  8192
#define D_    128
#define G_    8
#define P_    1024
#define MK_   34
#define S_    (G_*MK_)
#define BH_   (B_*H_)

#define SCALE_F 0.08838834764831843f
#define LN8_F   2.0794415416798357f
#define TINY_F  1.17549435e-38f
#define EPS_F   1.1920929e-07f

// smem layout (floats) for attn kernel
#define O_QH 0
#define O_QL 8448
#define O_KH 16896
#define O_KL 25344
#define O_VH 33792
#define O_VL 42496
#define O_PS 51200
#define O_RED 55552
#define SMEM_FLOATS 55808
#define SMEM_B (SMEM_FLOATS*4)

__device__ __align__(16) float g_qrep [BH_*P_*D_];
__device__ __align__(16) float g_krep [BH_*P_*D_];
__device__ __align__(16) float g_vmean[BH_*P_*D_];
__device__ __align__(16) float g_attn1[BH_*P_*D_];
__device__ __align__(16) float g_adel [BH_*P_*D_];
__device__ __align__(16) float g_aadd [BH_*P_*D_];
__device__ float g_lse1[BH_*P_];
__device__ float g_ldel[BH_*P_];
__device__ float g_ladd[BH_*P_];
__device__ float g_score_k[BH_*G_*P_];
__device__ float g_score_q[BH_*G_*P_];
__device__ int   g_kidx[BH_*G_*MK_];
__device__ int   g_qidx[BH_*G_*MK_];
__device__ __align__(16) float g_ksub   [BH_*S_*D_];
__device__ __align__(16) float g_krepsub[BH_*S_*D_];
__device__ __align__(16) float g_vsub   [BH_*S_*D_];
__device__ __align__(16) float g_qsub   [BH_*S_*D_];
__device__ __align__(16) float g_a2     [BH_*S_*D_];
__device__ float g_l2[BH_*S_];
__device__ __align__(16) float g_part_o[(size_t)8*BH_*320*D_];
__device__ float g_part_l[8*BH_*320];

__device__ __forceinline__ uint32_t to_tf32(float x) {
  uint32_t r; asm("cvt.rn.tf32.f32 %0, %1;" : "=r"(r) : "f"(x)); return r;
}

#define MMA(d,a,b0,b1) \
  asm volatile("mma.sync.aligned.m16n8k8.row.col.f32.tf32.tf32.f32 " \
  "{%0,%1,%2,%3},{%4,%5,%6,%7},{%8,%9},{%0,%1,%2,%3};" \
  : "+f"((d)[0]),"+f"((d)[1]),"+f"((d)[2]),"+f"((d)[3]) \
  : "r"((a)[0]),"r"((a)[1]),"r"((a)[2]),"r"((a)[3]),"r"(b0),"r"(b1))

// ---------------- threefry2x32 ----------------
__device__ __forceinline__ void threefry2x32(uint32_t k0, uint32_t k1,
                                             uint32_t x0, uint32_t x1,
                                             uint32_t& o0, uint32_t& o1) {
  uint32_t k2 = k0 ^ k1 ^ 0x1BD11BDAu;
  x0 += k0; x1 += k1;
#define TFR(r) { x0 += x1; x1 = (x1 << (r)) | (x1 >> (32 - (r))); x1 ^= x0; }
  TFR(13) TFR(15) TFR(26) TFR(6)   x0 += k1; x1 += k2 + 1u;
  TFR(17) TFR(29) TFR(16) TFR(24)  x0 += k2; x1 += k0 + 2u;
  TFR(13) TFR(15) TFR(26) TFR(6)   x0 += k0; x1 += k1 + 3u;
  TFR(17) TFR(29) TFR(16) TFR(24)  x0 += k1; x1 += k2 + 4u;
  TFR(13) TFR(15) TFR(26) TFR(6)   x0 += k2; x1 += k0 + 5u;
#undef TFR
  o0 = x0; o1 = x1;
}

// ---------------- means ----------------
__global__ void __launch_bounds__(256) means_kernel(const float* __restrict__ q,
                                                    const float* __restrict__ k,
                                                    const float* __restrict__ v) {
  int idx = blockIdx.x * 256 + threadIdx.x;
  int bh  = idx / (P_*32);
  int rem = idx - bh * (P_*32);
  const float4* q4 = (const float4*)q + (size_t)bh*NTOK*32 + rem;
  const float4* k4 = (const float4*)k + (size_t)bh*NTOK*32 + rem;
  const float4* v4 = (const float4*)v + (size_t)bh*NTOK*32 + rem;
  float4 sq = make_float4(0,0,0,0), sk = sq, sv = sq;
#pragma unroll
  for (int g = 0; g < G_; g++) {
    float4 a = q4[(size_t)g*P_*32]; sq.x+=a.x; sq.y+=a.y; sq.z+=a.z; sq.w+=a.w;
    float4 b = k4[(size_t)g*P_*32]; sk.x+=b.x; sk.y+=b.y; sk.z+=b.z; sk.w+=b.w;
    float4 c = v4[(size_t)g*P_*32]; sv.x+=c.x; sv.y+=c.y; sv.z+=c.z; sv.w+=c.w;
  }
  const float s = 1.0f / G_;
  sq.x*=s; sq.y*=s; sq.z*=s; sq.w*=s;
  sk.x*=s; sk.y*=s; sk.z*=s; sk.w*=s;
  sv.x*=s; sv.y*=s; sv.z*=s; sv.w*=s;
  ((float4*)g_qrep )[idx] = sq;
  ((float4*)g_krep )[idx] = sk;
  ((float4*)g_vmean)[idx] = sv;
}

// ---------------- scores ----------------
__global__ void __launch_bounds__(256) scores_kernel(const float* __restrict__ q,
                                                     const float* __restrict__ k) {
  unsigned wi = (blockIdx.x * 256u + threadIdx.x) >> 5;
  int lane = threadIdx.x & 31;
  const unsigned RT = (unsigned)(BH_*G_*P_);
  int t = wi >= RT;
  unsigned r  = t ? wi - RT : wi;
  unsigned bh = r >> 13;
  unsigned g  = (r >> 10) & 7u;
  unsigned j  = r & 1023u;
  const float* x  = (t ? q : k)           + (((size_t)bh*NTOK + g*P_ + j) << 7);
  const float* rp = (t ? g_qrep : g_krep) + (((size_t)bh*P_ + j) << 7);
  float4 a = *(const float4*)(x  + lane*4);
  float4 b = *(const float4*)(rp + lane*4);
  float dx=a.x-b.x, dy=a.y-b.y, dz=a.z-b.z, dw=a.w-b.w;
  float ss = dx*dx + dy*dy + dz*dz + dw*dw;
#pragma unroll
  for (int off = 16; off; off >>= 1)
    ss += __shfl_xor_sync(0xffffffffu, ss, off);
  if (lane == 0) {
    uint32_t rk0, rk1, o0, o1;
    threefry2x32(0u, 42u, 0u, (uint32_t)t, rk0, rk1);
    threefry2x32(rk0, rk1, 0u, r, o0, o1);
    uint32_t bits = o0 ^ o1;
    float u = __uint_as_float((bits >> 9) | 0x3f800000u) - 1.0f;
    if (u <= 0.0f) u = TINY_F;
    float gum = -logf(-logf(u));
    float score = logf(sqrtf(ss) * 100.0f + EPS_F) + gum;
    (t ? g_score_q : g_score_k)[r] = score;
  }
}

// ---------------- top-34 ----------------
__global__ void __launch_bounds__(256) topk_kernel() {
  int grp = blockIdx.x;
  int t   = blockIdx.y;
  float* sc = (t ? g_score_q : g_score_k) + (size_t)grp * P_;
  int*  out = (t ? g_qidx    : g_kidx   ) + (size_t)grp * MK_;
  __shared__ float sv[1024];
  __shared__ float rv[256];
  __shared__ int   ri[256];
  int tid = threadIdx.x;
#pragma unroll
  for (int r = 0; r < 4; r++) sv[tid + 256*r] = sc[tid + 256*r];
  __syncthreads();
  for (int it = 0; it < MK_; it++) {
    float bv = -INFINITY; int bi = 0x7fffffff;
#pragma unroll
    for (int r = 0; r < 4; r++) {
      int i = tid + 256*r;
      float vv = sv[i];
      if (vv > bv || (vv == bv && i < bi)) { bv = vv; bi = i; }
    }
    rv[tid] = bv; ri[tid] = bi;
    __syncthreads();
    for (int s = 128; s; s >>= 1) {
      if (tid < s) {
        float vv = rv[tid+s]; int i2 = ri[tid+s];
        if (vv > rv[tid] || (vv == rv[tid] && i2 < ri[tid])) { rv[tid]=vv; ri[tid]=i2; }
      }
      __syncthreads();
    }
    if (tid == 0) { out[it] = ri[0]; sv[ri[0]] = -INFINITY; }
    __syncthreads();
  }
}

// ---------------- gathers ----------------
__global__ void __launch_bounds__(256) gather_kernel(const float* __restrict__ q,
                                                     const float* __restrict__ k,
                                                     const float* __restrict__ v) {
  unsigned wi = (blockIdx.x * 256u + threadIdx.x) >> 5;
  int lane = threadIdx.x & 31;
  if (wi >= (unsigned)(BH_*S_)) return;
  int bh = wi / S_;
  int rr = wi % S_;
  int g = rr / MK_, tt = rr % MK_;
  int kj = g_kidx[(bh*G_+g)*MK_+tt];
  int qj = g_qidx[(bh*G_+g)*MK_+tt];
  size_t srck = ((size_t)bh*NTOK + g*P_ + kj) << 7;
  size_t srcq = ((size_t)bh*NTOK + g*P_ + qj) << 7;
  size_t dst  = ((size_t)wi << 7) + lane*4;
  *(float4*)(g_ksub    + dst) = *(const float4*)(k + srck + lane*4);
  *(float4*)(g_vsub    + dst) = *(const float4*)(v + srck + lane*4);
  *(float4*)(g_krepsub + dst) = *(const float4*)(g_krep + (((size_t)bh*P_ + kj) << 7) + lane*4);
  *(float4*)(g_qsub    + dst) = *(const float4*)(q + srcq + lane*4);
}

// ---------------- mma.sync TF32 flash attention ----------------
// modes: 0 p0, 1 p1-del, 2 p1-add, 3 p2(split-K partials)
__global__ void __launch_bounds__(256, 1)
attn_mma_kernel(int mode, const float* __restrict__ kin, const float* __restrict__ vin) {
  extern __shared__ float sm[];
  float* Qh = sm + O_QH; float* Ql = sm + O_QL;
  float* Kh = sm + O_KH; float* Kl = sm + O_KL;
  float* Vh = sm + O_VH; float* Vl = sm + O_VL;
  float* Ps = sm + O_PS; float* red = sm + O_RED;
  const uint32_t* Qhw = (const uint32_t*)Qh;
  const uint32_t* Qlw = (const uint32_t*)Ql;
  const uint32_t* Khw = (const uint32_t*)Kh;
  const uint32_t* Klw = (const uint32_t*)Kl;
  const uint32_t* Vhw = (const uint32_t*)Vh;
  const uint32_t* Vlw = (const uint32_t*)Vl;
  const uint32_t* Pw  = (const uint32_t*)Ps;

  int tid = threadIdx.x;
  int w = tid >> 5, lane = tid & 31;
  int gr = lane >> 2, gc = lane & 3;
  int wq = w & 1, wd = w >> 1;     // wd doubles as wk for S
  int bh = blockIdx.z;

  const float *Qs, *Ks, *Vs; float *dO, *dL;
  int nq, ke, ntile, k0;
  if (mode == 0) { Qs=g_qrep+(size_t)bh*P_*D_; Ks=g_krep+(size_t)bh*P_*D_;  Vs=g_vmean+(size_t)bh*P_*D_;
                   nq=P_; ke=P_; ntile=16; k0=0; dO=g_attn1; dL=g_lse1; }
  else if (mode==1){Qs=g_qrep+(size_t)bh*P_*D_; Ks=g_krepsub+(size_t)bh*S_*D_; Vs=g_vsub+(size_t)bh*S_*D_;
                   nq=P_; ke=S_; ntile=5; k0=0; dO=g_adel; dL=g_ldel; }
  else if (mode==2){Qs=g_qrep+(size_t)bh*P_*D_; Ks=g_ksub+(size_t)bh*S_*D_;  Vs=g_vsub+(size_t)bh*S_*D_;
                   nq=P_; ke=S_; ntile=5; k0=0; dO=g_aadd; dL=g_ladd; }
  else           { Qs=g_qsub+(size_t)bh*S_*D_; Ks=kin+(size_t)bh*NTOK*D_;   Vs=vin+(size_t)bh*NTOK*D_;
                   nq=S_; k0=blockIdx.y*1024; ke=k0+1024; ntile=16; dO=0; dL=0; }
  int q0 = blockIdx.x * 64;

  // stage Q hi/lo (scaled, row-clamped)
#pragma unroll
  for (int t = 0; t < 8; t++) {
    int idx = tid + t*256;
    int row = idx >> 5, c4 = (idx & 31)*4;
    int gq = q0 + row; if (gq > nq-1) gq = nq-1;
    float4 v = *(const float4*)(Qs + ((size_t)gq << 7) + c4);
    v.x*=SCALE_F; v.y*=SCALE_F; v.z*=SCALE_F; v.w*=SCALE_F;
    uint4 h, l;
    h.x=to_tf32(v.x); l.x=to_tf32(v.x-__uint_as_float(h.x));
    h.y=to_tf32(v.y); l.y=to_tf32(v.y-__uint_as_float(h.y));
    h.z=to_tf32(v.z); l.z=to_tf32(v.z-__uint_as_float(h.z));
    h.w=to_tf32(v.w); l.w=to_tf32(v.w-__uint_as_float(h.w));
    *(uint4*)(Qh + row*132 + c4) = h;
    *(uint4*)(Ql + row*132 + c4) = l;
  }

  float oacc[2][4][4];
#pragma unroll
  for (int m=0;m<2;m++)
#pragma unroll
    for (int n=0;n<4;n++)
#pragma unroll
      for (int i=0;i<4;i++) oacc[m][n][i]=0.f;
  float psum[4] = {0.f,0.f,0.f,0.f};

  for (int tile = 0; tile < ntile; tile++) {
    int kb = k0 + tile*64;
    __syncthreads();
    // stage K,V hi/lo
#pragma unroll
    for (int t = 0; t < 8; t++) {
      int idx = tid + t*256;
      int row = idx >> 5, c4 = (idx & 31)*4;
      int gk = kb + row;
      float4 kv = make_float4(0,0,0,0), vv = kv;
      if (gk < ke) {
        kv = *(const float4*)(Ks + ((size_t)gk << 7) + c4);
        vv = *(const float4*)(Vs + ((size_t)gk << 7) + c4);
      }
      uint4 h, l;
      h.x=to_tf32(kv.x); l.x=to_tf32(kv.x-__uint_as_float(h.x));
      h.y=to_tf32(kv.y); l.y=to_tf32(kv.y-__uint_as_float(h.y));
      h.z=to_tf32(kv.z); l.z=to_tf32(kv.z-__uint_as_float(h.z));
      h.w=to_tf32(kv.w); l.w=to_tf32(kv.w-__uint_as_float(h.w));
      *(uint4*)(Kh + row*132 + c4) = h;
      *(uint4*)(Kl + row*132 + c4) = l;
      h.x=to_tf32(vv.x); l.x=to_tf32(vv.x-__uint_as_float(h.x));
      h.y=to_tf32(vv.y); l.y=to_tf32(vv.y-__uint_as_float(h.y));
      h.z=to_tf32(vv.z); l.z=to_tf32(vv.z-__uint_as_float(h.z));
      h.w=to_tf32(vv.w); l.w=to_tf32(vv.w-__uint_as_float(h.w));
      *(uint4*)(Vh + row*136 + c4) = h;
      *(uint4*)(Vl + row*136 + c4) = l;
    }
    __syncthreads();

    // S = Q K^T : warp tile 32q x 16k, 3-pass split
    float sacc[2][2][4];
#pragma unroll
    for (int m=0;m<2;m++)
#pragma unroll
      for (int n=0;n<2;n++)
#pragma unroll
        for (int i=0;i<4;i++) sacc[m][n][i]=0.f;
#pragma unroll 4
    for (int ks = 0; ks < 16; ks++) {
      int ca = ks*8 + gc;
      uint32_t ah[2][4], al[2][4];
#pragma unroll
      for (int m = 0; m < 2; m++) {
        int r0 = (wq*32 + m*16 + gr)*132, r1 = r0 + 8*132;
        ah[m][0]=Qhw[r0+ca]; ah[m][1]=Qhw[r1+ca]; ah[m][2]=Qhw[r0+ca+4]; ah[m][3]=Qhw[r1+ca+4];
        al[m][0]=Qlw[r0+ca]; al[m][1]=Qlw[r1+ca]; al[m][2]=Qlw[r0+ca+4]; al[m][3]=Qlw[r1+ca+4];
      }
#pragma unroll
      for (int n = 0; n < 2; n++) {
        int nb = (wd*16 + n*8 + gr)*132;
        uint32_t bh0 = Khw[nb+ca], bh1 = Khw[nb+ca+4];
        uint32_t bl0 = Klw[nb+ca], bl1 = Klw[nb+ca+4];
#pragma unroll
        for (int m = 0; m < 2; m++) {
          MMA(sacc[m][n], ah[m], bh0, bh1);
          MMA(sacc[m][n], ah[m], bl0, bl1);
          MMA(sacc[m][n], al[m], bh0, bh1);
        }
      }
    }
    // exp + psum + store P (tf32)
#pragma unroll
    for (int m = 0; m < 2; m++) {
#pragma unroll
      for (int n = 0; n < 2; n++) {
        int colb = wd*16 + n*8 + 2*gc;
        int gcol = kb + colb;
        float p0 = (gcol   < ke) ? __expf(sacc[m][n][0]) : 0.f;
        float p1 = (gcol+1 < ke) ? __expf(sacc[m][n][1]) : 0.f;
        float p2 = (gcol   < ke) ? __expf(sacc[m][n][2]) : 0.f;
        float p3 = (gcol+1 < ke) ? __expf(sacc[m][n][3]) : 0.f;
        psum[m*2]   += p0 + p1;
        psum[m*2+1] += p2 + p3;
        int r0 = wq*32 + m*16 + gr;
        uint2 w0; w0.x = to_tf32(p0); w0.y = to_tf32(p1);
        uint2 w1; w1.x = to_tf32(p2); w1.y = to_tf32(p3);
        *(uint2*)(Ps + r0*68 + colb)     = w0;
        *(uint2*)(Ps + (r0+8)*68 + colb) = w1;
      }
    }
    __syncthreads();
    // O += P V : warp tile 32q x 32d, 2-pass (Vh, Vl)
#pragma unroll 4
    for (int ks = 0; ks < 8; ks++) {
      int ca = ks*8 + gc;
      uint32_t pa[2][4];
#pragma unroll
      for (int m = 0; m < 2; m++) {
        int r0 = (wq*32 + m*16 + gr)*68, r1 = r0 + 8*68;
        pa[m][0]=Pw[r0+ca]; pa[m][1]=Pw[r1+ca]; pa[m][2]=Pw[r0+ca+4]; pa[m][3]=Pw[r1+ca+4];
      }
#pragma unroll
      for (int n = 0; n < 4; n++) {
        int nb = wd*32 + n*8 + gr;
        uint32_t bh0 = Vhw[ca*136 + nb], bh1 = Vhw[(ca+4)*136 + nb];
        uint32_t bl0 = Vlw[ca*136 + nb], bl1 = Vlw[(ca+4)*136 + nb];
#pragma unroll
        for (int m = 0; m < 2; m++) {
          MMA(oacc[m][n], pa[m], bh0, bh1);
          MMA(oacc[m][n], pa[m], bl0, bl1);
        }
      }
    }
  }

  // reduce psum across gc lanes, publish per (wq, wk=wd) partials
#pragma unroll
  for (int s = 0; s < 4; s++) {
    psum[s] += __shfl_xor_sync(0xffffffffu, psum[s], 1);
    psum[s] += __shfl_xor_sync(0xffffffffu, psum[s], 2);
  }
  __syncthreads();
  if (gc == 0) {
#pragma unroll
    for (int s = 0; s < 4; s++) {
      int rl = (s>>1)*16 + gr + (s&1)*8;
      red[(wq*4 + wd)*32 + rl] = psum[s];
    }
  }
  __syncthreads();
  float Lr[4], iv[4];
#pragma unroll
  for (int s = 0; s < 4; s++) {
    int rl = (s>>1)*16 + gr + (s&1)*8;
    float L = red[(wq*4+0)*32+rl] + red[(wq*4+1)*32+rl] +
              red[(wq*4+2)*32+rl] + red[(wq*4+3)*32+rl];
    Lr[s] = L; iv[s] = 1.0f / L;
  }
  if (mode < 3) {
#pragma unroll
    for (int m = 0; m < 2; m++) {
      int row = q0 + wq*32 + m*16 + gr;
#pragma unroll
      for (int n = 0; n < 4; n++) {
        int col = wd*32 + n*8 + 2*gc;
        float2 a = make_float2(oacc[m][n][0]*iv[2*m],   oacc[m][n][1]*iv[2*m]);
        float2 b = make_float2(oacc[m][n][2]*iv[2*m+1], oacc[m][n][3]*iv[2*m+1]);
        *(float2*)(dO + (((size_t)bh*nq + row)   << 7) + col) = a;
        *(float2*)(dO + (((size_t)bh*nq + row+8) << 7) + col) = b;
      }
    }
    if (wd == 0 && gc == 0) {
#pragma unroll
      for (int s = 0; s < 4; s++) {
        int rl = (s>>1)*16 + gr + (s&1)*8;
        dL[(size_t)bh*nq + q0 + wq*32 + rl] = logf(Lr[s]);
      }
    }
  } else {
    size_t pb = (size_t)(blockIdx.y*BH_ + bh)*320 + q0;
#pragma unroll
    for (int m = 0; m < 2; m++) {
      int rl = wq*32 + m*16 + gr;
#pragma unroll
      for (int n = 0; n < 4; n++) {
        int col = wd*32 + n*8 + 2*gc;
        *(float2*)(g_part_o + ((pb + rl)   << 7) + col) = make_float2(oacc[m][n][0], oacc[m][n][1]);
        *(float2*)(g_part_o + ((pb + rl+8) << 7) + col) = make_float2(oacc[m][n][2], oacc[m][n][3]);
      }
    }
    if (wd == 0 && gc == 0) {
#pragma unroll
      for (int s = 0; s < 4; s++) {
        int rl = (s>>1)*16 + gr + (s&1)*8;
        g_part_l[pb + wq*32 + rl] = Lr[s];
      }
    }
  }
}

// ---------------- p2 merge ----------------
__global__ void __launch_bounds__(256) merge3_kernel() {
  int bh = blockIdx.y;
  int w = threadIdx.x >> 5, lane = threadIdx.x & 31;
  int row = blockIdx.x*8 + w;
  if (row >= S_) return;
  float L = 0.f;
  float4 o = make_float4(0,0,0,0);
#pragma unroll
  for (int s = 0; s < 8; s++) {
    size_t ri = (size_t)(s*BH_ + bh)*320 + row;
    L += g_part_l[ri];
    float4 po = *(const float4*)(g_part_o + (ri << 7) + lane*4);
    o.x += po.x; o.y += po.y; o.z += po.z; o.w += po.w;
  }
  float inv = 1.0f / L;
  o.x*=inv; o.y*=inv; o.z*=inv; o.w*=inv;
  *(float4*)(g_a2 + (((size_t)bh*S_ + row) << 7) + lane*4) = o;
  if (lane == 0) g_l2[(size_t)bh*S_ + row] = logf(L);
}

// ---------------- p1 combine + broadcast ----------------
__global__ void __launch_bounds__(256) combine_kernel(float* __restrict__ out, int has_lse) {
  unsigned wi = (blockIdx.x * 256u + threadIdx.x) >> 5;
  int lane = threadIdx.x & 31;
  int bh = wi >> 10, j = wi & 1023;
  float l1 = g_lse1[wi] + LN8_F;
  float ld = g_ldel[wi];
  float la = g_ladd[wi];
  float c1 = expf(ld - l1);
  float inv1 = 1.0f / (1.0f - c1);
  float lp1 = l1 + log1pf(-c1);
  float c2 = 1.0f / (1.0f + expf(la - lp1));
  float lse = fmaxf(lp1, la) + log1pf(expf(-fabsf(lp1 - la)));
  size_t off = ((size_t)wi << 7) + lane*4;
  float4 a0 = *(const float4*)(g_attn1 + off);
  float4 ad = *(const float4*)(g_adel + off);
  float4 aa = *(const float4*)(g_aadd + off);
  float4 r;
  float c2b = 1.0f - c2;
  r.x = c2*((a0.x - c1*ad.x)*inv1) + c2b*aa.x;
  r.y = c2*((a0.y - c1*ad.y)*inv1) + c2b*aa.y;
  r.z = c2*((a0.z - c1*ad.z)*inv1) + c2b*aa.z;
  r.w = c2*((a0.w - c1*ad.w)*inv1) + c2b*aa.w;
  float* outl = out + (size_t)BH_*NTOK*D_;
#pragma unroll
  for (int g = 0; g < G_; g++) {
    size_t orow = (size_t)bh*NTOK + g*P_ + j;
    *(float4*)(out + (orow << 7) + lane*4) = r;
    if (lane == 0 && has_lse) outl[orow] = lse;
  }
}

// ---------------- p2 scatter ----------------
__global__ void __launch_bounds__(256) scatter_kernel(float* __restrict__ out, int has_lse) {
  unsigned wi = (blockIdx.x * 256u + threadIdx.x) >> 5;
  int lane = threadIdx.x & 31;
  if (wi >= (unsigned)(BH_*S_)) return;
  int bh = wi / S_;
  int rr = wi % S_;
  int g = rr / MK_, tt = rr % MK_;
  int qj = g_qidx[(bh*G_+g)*MK_+tt];
  size_t orow = (size_t)bh*NTOK + g*P_ + qj;
  float4 a = *(const float4*)(g_a2 + ((size_t)wi << 7) + lane*4);
  *(float4*)(out + (orow << 7) + lane*4) = a;
  if (lane == 0 && has_lse) out[(size_t)BH_*NTOK*D_ + orow] = g_l2[wi];
}

// ---------------- launch ----------------
extern "C" void kernel_launch(void* const* d_in, const int* in_sizes, int n_in,
                              void* d_out, int out_size) {
  const float* q = (const float*)d_in[0];
  const float* k = (const float*)d_in[1];
  const float* v = (const float*)d_in[2];
  float* out = (float*)d_out;
  int has_lse = (out_size >= BH_*NTOK*(D_ + 1)) ? 1 : 0;

  cudaFuncSetAttribute(attn_mma_kernel,
                       cudaFuncAttributeMaxDynamicSharedMemorySize, SMEM_B);

  means_kernel <<<(BH_*P_*32)/256, 256>>>(q, k, v);
  scores_kernel<<<(2*BH_*G_*P_*32)/256, 256>>>(q, k);
  topk_kernel  <<<dim3(BH_*G_, 2), 256>>>();
  gather_kernel<<<(BH_*S_*32 + 255)/256, 256>>>(q, k, v);

  attn_mma_kernel<<<dim3(16, 1, BH_), 256, SMEM_B>>>(0, nullptr, nullptr);
  attn_mma_kernel<<<dim3(16, 1, BH_), 256, SMEM_B>>>(1, nullptr, nullptr);
  attn_mma_kernel<<<dim3(16, 1, BH_), 256, SMEM_B>>>(2, nullptr, nullptr);
  attn_mma_kernel<<<dim3(5, 8, BH_), 256, SMEM_B>>>(3, k, v);
  merge3_kernel <<<dim3((S_+7)/8, BH_), 256>>>();

  combine_kernel<<<(BH_*P_*32)/256, 256>>>(out, has_lse);
  scatter_kernel<<<(BH_*S_*32 + 255)/256, 256>>>(out, has_lse);
}

// round 9
// speedup vs baseline: 4.1298x; 1.1362x over previous
#include <cuda_runtime.h>
#include <cuda_bf16.h>
#include <stdint.h>
#include <math.h>

#define B_    2
#define H_    16
#define NTOK  8192
#define D_    128
#define G_    8
#define P_    1024
#define MK_   34
#define S_    (G_*MK_)
#define BH_   (B_*H_)

#define SCALE_F 0.08838834764831843f
#define LN8_F   2.0794415416798357f
#define TINY_F  1.17549435e-38f
#define EPS_F   1.1920929e-07f

// smem u32 offsets
#define U_QH 0
#define U_QL 4096
#define U_KH 8192
#define U_KL 12288
#define U_VH 16384
#define U_VL 20480
#define U_PH 24576
#define U_PL 26624
#define U_RED 28672
#define SMEM_U 28928
#define SMEM_B (SMEM_U*4)

__device__ __align__(16) float g_qrep [BH_*P_*D_];
__device__ __align__(16) float g_krep [BH_*P_*D_];
__device__ __align__(16) float g_vmean[BH_*P_*D_];
__device__ __align__(16) float g_attn1[BH_*P_*D_];
__device__ __align__(16) float g_adel [BH_*P_*D_];
__device__ __align__(16) float g_aadd [BH_*P_*D_];
__device__ float g_lse1[BH_*P_];
__device__ float g_ldel[BH_*P_];
__device__ float g_ladd[BH_*P_];
__device__ float g_score_k[BH_*G_*P_];
__device__ float g_score_q[BH_*G_*P_];
__device__ int   g_kidx[BH_*G_*MK_];
__device__ int   g_qidx[BH_*G_*MK_];
__device__ __align__(16) float g_ksub   [BH_*S_*D_];
__device__ __align__(16) float g_krepsub[BH_*S_*D_];
__device__ __align__(16) float g_vsub   [BH_*S_*D_];
__device__ __align__(16) float g_qsub   [BH_*S_*D_];
__device__ __align__(16) float g_a2     [BH_*S_*D_];
__device__ float g_l2[BH_*S_];
__device__ __align__(16) float g_part_o[(size_t)8*BH_*320*D_];
__device__ float g_part_l[8*BH_*320];

// pack two floats -> bf16x2 hi, plus bf16x2 of residuals
__device__ __forceinline__ void split2(float x0, float x1, uint32_t& hp, uint32_t& lp) {
  __nv_bfloat162 h = __floats2bfloat162_rn(x0, x1);
  hp = *reinterpret_cast<uint32_t*>(&h);
  float h0 = __uint_as_float(hp << 16);
  float h1 = __uint_as_float(hp & 0xffff0000u);
  __nv_bfloat162 l = __floats2bfloat162_rn(x0 - h0, x1 - h1);
  lp = *reinterpret_cast<uint32_t*>(&l);
}

#define MMAB(d,a,b0,b1) \
  asm volatile("mma.sync.aligned.m16n8k16.row.col.f32.bf16.bf16.f32 " \
  "{%0,%1,%2,%3},{%4,%5,%6,%7},{%8,%9},{%0,%1,%2,%3};" \
  : "+f"((d)[0]),"+f"((d)[1]),"+f"((d)[2]),"+f"((d)[3]) \
  : "r"((a)[0]),"r"((a)[1]),"r"((a)[2]),"r"((a)[3]),"r"(b0),"r"(b1))

// ---------------- threefry2x32 ----------------
__device__ __forceinline__ void threefry2x32(uint32_t k0, uint32_t k1,
                                             uint32_t x0, uint32_t x1,
                                             uint32_t& o0, uint32_t& o1) {
  uint32_t k2 = k0 ^ k1 ^ 0x1BD11BDAu;
  x0 += k0; x1 += k1;
#define TFR(r) { x0 += x1; x1 = (x1 << (r)) | (x1 >> (32 - (r))); x1 ^= x0; }
  TFR(13) TFR(15) TFR(26) TFR(6)   x0 += k1; x1 += k2 + 1u;
  TFR(17) TFR(29) TFR(16) TFR(24)  x0 += k2; x1 += k0 + 2u;
  TFR(13) TFR(15) TFR(26) TFR(6)   x0 += k0; x1 += k1 + 3u;
  TFR(17) TFR(29) TFR(16) TFR(24)  x0 += k1; x1 += k2 + 4u;
  TFR(13) TFR(15) TFR(26) TFR(6)   x0 += k2; x1 += k0 + 5u;
#undef TFR
  o0 = x0; o1 = x1;
}

// ---------------- means ----------------
__global__ void __launch_bounds__(256) means_kernel(const float* __restrict__ q,
                                                    const float* __restrict__ k,
                                                    const float* __restrict__ v) {
  int idx = blockIdx.x * 256 + threadIdx.x;
  int bh  = idx / (P_*32);
  int rem = idx - bh * (P_*32);
  const float4* q4 = (const float4*)q + (size_t)bh*NTOK*32 + rem;
  const float4* k4 = (const float4*)k + (size_t)bh*NTOK*32 + rem;
  const float4* v4 = (const float4*)v + (size_t)bh*NTOK*32 + rem;
  float4 sq = make_float4(0,0,0,0), sk = sq, sv = sq;
#pragma unroll
  for (int g = 0; g < G_; g++) {
    float4 a = q4[(size_t)g*P_*32]; sq.x+=a.x; sq.y+=a.y; sq.z+=a.z; sq.w+=a.w;
    float4 b = k4[(size_t)g*P_*32]; sk.x+=b.x; sk.y+=b.y; sk.z+=b.z; sk.w+=b.w;
    float4 c = v4[(size_t)g*P_*32]; sv.x+=c.x; sv.y+=c.y; sv.z+=c.z; sv.w+=c.w;
  }
  const float s = 1.0f / G_;
  sq.x*=s; sq.y*=s; sq.z*=s; sq.w*=s;
  sk.x*=s; sk.y*=s; sk.z*=s; sk.w*=s;
  sv.x*=s; sv.y*=s; sv.z*=s; sv.w*=s;
  ((float4*)g_qrep )[idx] = sq;
  ((float4*)g_krep )[idx] = sk;
  ((float4*)g_vmean)[idx] = sv;
}

// ---------------- scores ----------------
__global__ void __launch_bounds__(256) scores_kernel(const float* __restrict__ q,
                                                     const float* __restrict__ k) {
  unsigned wi = (blockIdx.x * 256u + threadIdx.x) >> 5;
  int lane = threadIdx.x & 31;
  const unsigned RT = (unsigned)(BH_*G_*P_);
  int t = wi >= RT;
  unsigned r  = t ? wi - RT : wi;
  unsigned bh = r >> 13;
  unsigned g  = (r >> 10) & 7u;
  unsigned j  = r & 1023u;
  const float* x  = (t ? q : k)           + (((size_t)bh*NTOK + g*P_ + j) << 7);
  const float* rp = (t ? g_qrep : g_krep) + (((size_t)bh*P_ + j) << 7);
  float4 a = *(const float4*)(x  + lane*4);
  float4 b = *(const float4*)(rp + lane*4);
  float dx=a.x-b.x, dy=a.y-b.y, dz=a.z-b.z, dw=a.w-b.w;
  float ss = dx*dx + dy*dy + dz*dz + dw*dw;
#pragma unroll
  for (int off = 16; off; off >>= 1)
    ss += __shfl_xor_sync(0xffffffffu, ss, off);
  if (lane == 0) {
    uint32_t rk0, rk1, o0, o1;
    threefry2x32(0u, 42u, 0u, (uint32_t)t, rk0, rk1);
    threefry2x32(rk0, rk1, 0u, r, o0, o1);
    uint32_t bits = o0 ^ o1;
    float u = __uint_as_float((bits >> 9) | 0x3f800000u) - 1.0f;
    if (u <= 0.0f) u = TINY_F;
    float gum = -logf(-logf(u));
    float score = logf(sqrtf(ss) * 100.0f + EPS_F) + gum;
    (t ? g_score_q : g_score_k)[r] = score;
  }
}

// ---------------- top-34 ----------------
__global__ void __launch_bounds__(256) topk_kernel() {
  int grp = blockIdx.x;
  int t   = blockIdx.y;
  float* sc = (t ? g_score_q : g_score_k) + (size_t)grp * P_;
  int*  out = (t ? g_qidx    : g_kidx   ) + (size_t)grp * MK_;
  __shared__ float sv[1024];
  __shared__ float rv[256];
  __shared__ int   ri[256];
  int tid = threadIdx.x;
#pragma unroll
  for (int r = 0; r < 4; r++) sv[tid + 256*r] = sc[tid + 256*r];
  __syncthreads();
  for (int it = 0; it < MK_; it++) {
    float bv = -INFINITY; int bi = 0x7fffffff;
#pragma unroll
    for (int r = 0; r < 4; r++) {
      int i = tid + 256*r;
      float vv = sv[i];
      if (vv > bv || (vv == bv && i < bi)) { bv = vv; bi = i; }
    }
    rv[tid] = bv; ri[tid] = bi;
    __syncthreads();
    for (int s = 128; s; s >>= 1) {
      if (tid < s) {
        float vv = rv[tid+s]; int i2 = ri[tid+s];
        if (vv > rv[tid] || (vv == rv[tid] && i2 < ri[tid])) { rv[tid]=vv; ri[tid]=i2; }
      }
      __syncthreads();
    }
    if (tid == 0) { out[it] = ri[0]; sv[ri[0]] = -INFINITY; }
    __syncthreads();
  }
}

// ---------------- gathers ----------------
__global__ void __launch_bounds__(256) gather_kernel(const float* __restrict__ q,
                                                     const float* __restrict__ k,
                                                     const float* __restrict__ v) {
  unsigned wi = (blockIdx.x * 256u + threadIdx.x) >> 5;
  int lane = threadIdx.x & 31;
  if (wi >= (unsigned)(BH_*S_)) return;
  int bh = wi / S_;
  int rr = wi % S_;
  int g = rr / MK_, tt = rr % MK_;
  int kj = g_kidx[(bh*G_+g)*MK_+tt];
  int qj = g_qidx[(bh*G_+g)*MK_+tt];
  size_t srck = ((size_t)bh*NTOK + g*P_ + kj) << 7;
  size_t srcq = ((size_t)bh*NTOK + g*P_ + qj) << 7;
  size_t dst  = ((size_t)wi << 7) + lane*4;
  *(float4*)(g_ksub    + dst) = *(const float4*)(k + srck + lane*4);
  *(float4*)(g_vsub    + dst) = *(const float4*)(v + srck + lane*4);
  *(float4*)(g_krepsub + dst) = *(const float4*)(g_krep + (((size_t)bh*P_ + kj) << 7) + lane*4);
  *(float4*)(g_qsub    + dst) = *(const float4*)(q + srcq + lane*4);
}

// ---------------- unified bf16x3 mma flash attention ----------------
// blocks: [0,1280) p2 ; [1280,1792) p0 ; [1792,2304) p1-del ; [2304,2816) p1-add
__global__ void __launch_bounds__(256, 1)
attn_bf16_kernel(const float* __restrict__ kin, const float* __restrict__ vin) {
  extern __shared__ uint32_t su[];
  uint32_t* Qh = su + U_QH; uint32_t* Ql = su + U_QL;
  uint32_t* Kh = su + U_KH; uint32_t* Kl = su + U_KL;
  uint32_t* Vth = su + U_VH; uint32_t* Vtl = su + U_VL;
  uint32_t* Php = su + U_PH; uint32_t* Plp = su + U_PL;
  float* red = (float*)(su + U_RED);

  int tid = threadIdx.x;
  int w = tid >> 5, lane = tid & 31;
  int gr = lane >> 2, gc = lane & 3;
  int wq = w & 1, wd = w >> 1;

  int i = blockIdx.x;
  int mode, bh, qb, sp = 0;
  if (i < 1280) { mode = 3; sp = i / 160; int r = i - sp*160; bh = r / 5; qb = r - bh*5; }
  else { int j = i - 1280; mode = j >> 9; bh = (j >> 4) & 31; qb = j & 15; }

  const float *Qs, *Ks, *Vs; float *dO, *dL;
  int nq, ke, ntile, k0;
  if (mode == 0) { Qs=g_qrep+(size_t)bh*P_*D_; Ks=g_krep+(size_t)bh*P_*D_;  Vs=g_vmean+(size_t)bh*P_*D_;
                   nq=P_; ke=P_; ntile=16; k0=0; dO=g_attn1; dL=g_lse1; }
  else if (mode==1){Qs=g_qrep+(size_t)bh*P_*D_; Ks=g_krepsub+(size_t)bh*S_*D_; Vs=g_vsub+(size_t)bh*S_*D_;
                   nq=P_; ke=S_; ntile=5; k0=0; dO=g_adel; dL=g_ldel; }
  else if (mode==2){Qs=g_qrep+(size_t)bh*P_*D_; Ks=g_ksub+(size_t)bh*S_*D_;  Vs=g_vsub+(size_t)bh*S_*D_;
                   nq=P_; ke=S_; ntile=5; k0=0; dO=g_aadd; dL=g_ladd; }
  else           { Qs=g_qsub+(size_t)bh*S_*D_; Ks=kin+(size_t)bh*NTOK*D_;   Vs=vin+(size_t)bh*NTOK*D_;
                   nq=S_; k0=sp*1024; ke=k0+1024; ntile=16; dO=0; dL=0; }
  int q0 = qb * 64;

  // ---- stage Q hi/lo (scaled, clamped), pair-permuted + xor swizzle ----
#pragma unroll
  for (int t = 0; t < 8; t++) {
    int lin = tid + t*256;
    int row = lin >> 5, c4 = lin & 31;
    int gq = q0 + row; if (gq > nq-1) gq = nq-1;
    float4 v = *(const float4*)(Qs + ((size_t)gq << 7) + c4*4);
    v.x*=SCALE_F; v.y*=SCALE_F; v.z*=SCALE_F; v.w*=SCALE_F;
    uint32_t hp0,lp0,hp1,lp1;
    split2(v.x, v.y, hp0, lp0);
    split2(v.z, v.w, hp1, lp1);
    int r7 = row & 7;
    int j0 = 2*c4, j1 = j0+1;
    int col0 = (((j0>>3) ^ r7)<<3) + ((j0&3)<<1) + ((j0>>2)&1);
    int col1 = (((j1>>3) ^ r7)<<3) + ((j1&3)<<1) + ((j1>>2)&1);
    Qh[row*64+col0]=hp0; Ql[row*64+col0]=lp0;
    Qh[row*64+col1]=hp1; Ql[row*64+col1]=lp1;
  }

  float oacc[2][4][4];
#pragma unroll
  for (int m=0;m<2;m++)
#pragma unroll
    for (int n=0;n<4;n++)
#pragma unroll
      for (int t=0;t<4;t++) oacc[m][n][t]=0.f;
  float psum[4] = {0.f,0.f,0.f,0.f};

  int r0 = wq*32 + gr;
  int n0 = wd*16 + gr;
  int cx3 = gr & 3;

  for (int tile = 0; tile < ntile; tile++) {
    int kb = k0 + tile*64;
    __syncthreads();
    // stage K hi/lo
#pragma unroll
    for (int t = 0; t < 8; t++) {
      int lin = tid + t*256;
      int row = lin >> 5, c4 = lin & 31;
      int gk = kb + row;
      float4 v = make_float4(0,0,0,0);
      if (gk < ke) v = *(const float4*)(Ks + ((size_t)gk << 7) + c4*4);
      uint32_t hp0,lp0,hp1,lp1;
      split2(v.x, v.y, hp0, lp0);
      split2(v.z, v.w, hp1, lp1);
      int r7 = row & 7;
      int j0 = 2*c4, j1 = j0+1;
      int col0 = (((j0>>3) ^ r7)<<3) + ((j0&3)<<1) + ((j0>>2)&1);
      int col1 = (((j1>>3) ^ r7)<<3) + ((j1&3)<<1) + ((j1>>2)&1);
      Kh[row*64+col0]=hp0; Kl[row*64+col0]=lp0;
      Kh[row*64+col1]=hp1; Kl[row*64+col1]=lp1;
    }
    // stage V transposed pairs hi/lo
#pragma unroll
    for (int t = 0; t < 4; t++) {
      int lin = tid + t*256;
      int kp = lin & 31, dg = lin >> 5;
      int d0 = dg*4;
      int ka = kb + 2*kp;
      float4 va = make_float4(0,0,0,0), vb = va;
      if (ka   < ke) va = *(const float4*)(Vs + ((size_t)ka << 7) + d0);
      if (ka+1 < ke) vb = *(const float4*)(Vs + ((size_t)(ka+1) << 7) + d0);
      int cc = kp>>3, gg = kp&3, hh = (kp>>2)&1;
      uint32_t hp, lp;
      split2(va.x, vb.x, hp, lp);
      Vth[(d0+0)*32 + (((cc^0)<<3)+(gg<<1)+hh)] = hp; Vtl[(d0+0)*32 + (((cc^0)<<3)+(gg<<1)+hh)] = lp;
      split2(va.y, vb.y, hp, lp);
      Vth[(d0+1)*32 + (((cc^1)<<3)+(gg<<1)+hh)] = hp; Vtl[(d0+1)*32 + (((cc^1)<<3)+(gg<<1)+hh)] = lp;
      split2(va.z, vb.z, hp, lp);
      Vth[(d0+2)*32 + (((cc^2)<<3)+(gg<<1)+hh)] = hp; Vtl[(d0+2)*32 + (((cc^2)<<3)+(gg<<1)+hh)] = lp;
      split2(va.w, vb.w, hp, lp);
      Vth[(d0+3)*32 + (((cc^3)<<3)+(gg<<1)+hh)] = hp; Vtl[(d0+3)*32 + (((cc^3)<<3)+(gg<<1)+hh)] = lp;
    }
    __syncthreads();

    // ---- S = Q K^T (bf16 3-pass) ----
    float sacc[2][2][4];
#pragma unroll
    for (int m=0;m<2;m++)
#pragma unroll
      for (int n=0;n<2;n++)
#pragma unroll
        for (int t=0;t<4;t++) sacc[m][n][t]=0.f;
#pragma unroll
    for (int c = 0; c < 8; c++) {
      int cq = ((c ^ gr) << 3) + (gc << 1);
      uint2 aH[2][2], aL[2][2];
      aH[0][0] = *(const uint2*)(Qh + (r0   )*64 + cq);
      aH[0][1] = *(const uint2*)(Qh + (r0+8 )*64 + cq);
      aH[1][0] = *(const uint2*)(Qh + (r0+16)*64 + cq);
      aH[1][1] = *(const uint2*)(Qh + (r0+24)*64 + cq);
      aL[0][0] = *(const uint2*)(Ql + (r0   )*64 + cq);
      aL[0][1] = *(const uint2*)(Ql + (r0+8 )*64 + cq);
      aL[1][0] = *(const uint2*)(Ql + (r0+16)*64 + cq);
      aL[1][1] = *(const uint2*)(Ql + (r0+24)*64 + cq);
      uint2 bH[2], bL[2];
      bH[0] = *(const uint2*)(Kh + (n0  )*64 + cq);
      bH[1] = *(const uint2*)(Kh + (n0+8)*64 + cq);
      bL[0] = *(const uint2*)(Kl + (n0  )*64 + cq);
      bL[1] = *(const uint2*)(Kl + (n0+8)*64 + cq);
#pragma unroll
      for (int m = 0; m < 2; m++) {
        uint32_t Ah[4] = {aH[m][0].x, aH[m][1].x, aH[m][0].y, aH[m][1].y};
        uint32_t Al[4] = {aL[m][0].x, aL[m][1].x, aL[m][0].y, aL[m][1].y};
#pragma unroll
        for (int n = 0; n < 2; n++) {
          MMAB(sacc[m][n], Ah, bH[n].x, bH[n].y);
          MMAB(sacc[m][n], Ah, bL[n].x, bL[n].y);
          MMAB(sacc[m][n], Al, bH[n].x, bH[n].y);
        }
      }
    }
    // ---- exp + psum + store P hi/lo ----
#pragma unroll
    for (int m = 0; m < 2; m++) {
      int rm = wq*32 + m*16 + gr;
#pragma unroll
      for (int n = 0; n < 2; n++) {
        int colb = wd*16 + n*8 + 2*gc;
        int gcol = kb + colb;
        float p0 = (gcol   < ke) ? __expf(sacc[m][n][0]) : 0.f;
        float p1 = (gcol+1 < ke) ? __expf(sacc[m][n][1]) : 0.f;
        float p2 = (gcol   < ke) ? __expf(sacc[m][n][2]) : 0.f;
        float p3 = (gcol+1 < ke) ? __expf(sacc[m][n][3]) : 0.f;
        psum[m*2]   += p0 + p1;
        psum[m*2+1] += p2 + p3;
        int colp = ((wd ^ cx3)<<3) + (gc<<1) + n;
        uint32_t hp, lp;
        split2(p0, p1, hp, lp);
        Php[rm*32 + colp] = hp; Plp[rm*32 + colp] = lp;
        split2(p2, p3, hp, lp);
        Php[(rm+8)*32 + colp] = hp; Plp[(rm+8)*32 + colp] = lp;
      }
    }
    __syncthreads();
    // ---- O += P V (bf16 3-pass) ----
#pragma unroll
    for (int c = 0; c < 4; c++) {
      int cp = (((c ^ cx3) & 3) << 3) + (gc << 1);
      uint2 pH[2][2], pL[2][2];
      pH[0][0] = *(const uint2*)(Php + (r0   )*32 + cp);
      pH[0][1] = *(const uint2*)(Php + (r0+8 )*32 + cp);
      pH[1][0] = *(const uint2*)(Php + (r0+16)*32 + cp);
      pH[1][1] = *(const uint2*)(Php + (r0+24)*32 + cp);
      pL[0][0] = *(const uint2*)(Plp + (r0   )*32 + cp);
      pL[0][1] = *(const uint2*)(Plp + (r0+8 )*32 + cp);
      pL[1][0] = *(const uint2*)(Plp + (r0+16)*32 + cp);
      pL[1][1] = *(const uint2*)(Plp + (r0+24)*32 + cp);
      uint2 vH[4], vL[4];
      int dnb = wd*32 + gr;
#pragma unroll
      for (int n = 0; n < 4; n++) {
        vH[n] = *(const uint2*)(Vth + (dnb + n*8)*32 + cp);
        vL[n] = *(const uint2*)(Vtl + (dnb + n*8)*32 + cp);
      }
#pragma unroll
      for (int m = 0; m < 2; m++) {
        uint32_t Ph4[4] = {pH[m][0].x, pH[m][1].x, pH[m][0].y, pH[m][1].y};
        uint32_t Pl4[4] = {pL[m][0].x, pL[m][1].x, pL[m][0].y, pL[m][1].y};
#pragma unroll
        for (int n = 0; n < 4; n++) {
          MMAB(oacc[m][n], Ph4, vH[n].x, vH[n].y);
          MMAB(oacc[m][n], Ph4, vL[n].x, vL[n].y);
          MMAB(oacc[m][n], Pl4, vH[n].x, vH[n].y);
        }
      }
    }
  }

  // ---- psum reduce + epilogue ----
#pragma unroll
  for (int s = 0; s < 4; s++) {
    psum[s] += __shfl_xor_sync(0xffffffffu, psum[s], 1);
    psum[s] += __shfl_xor_sync(0xffffffffu, psum[s], 2);
  }
  __syncthreads();
  if (gc == 0) {
#pragma unroll
    for (int s = 0; s < 4; s++) {
      int rl = (s>>1)*16 + gr + (s&1)*8;
      red[(wq*4 + wd)*32 + rl] = psum[s];
    }
  }
  __syncthreads();
  float Lr[4], iv[4];
#pragma unroll
  for (int s = 0; s < 4; s++) {
    int rl = (s>>1)*16 + gr + (s&1)*8;
    float L = red[(wq*4+0)*32+rl] + red[(wq*4+1)*32+rl] +
              red[(wq*4+2)*32+rl] + red[(wq*4+3)*32+rl];
    Lr[s] = L; iv[s] = 1.0f / L;
  }
  if (mode < 3) {
#pragma unroll
    for (int m = 0; m < 2; m++) {
      int row = q0 + wq*32 + m*16 + gr;
#pragma unroll
      for (int n = 0; n < 4; n++) {
        int col = wd*32 + n*8 + 2*gc;
        float2 a = make_float2(oacc[m][n][0]*iv[2*m],   oacc[m][n][1]*iv[2*m]);
        float2 b = make_float2(oacc[m][n][2]*iv[2*m+1], oacc[m][n][3]*iv[2*m+1]);
        *(float2*)(dO + (((size_t)bh*nq + row)   << 7) + col) = a;
        *(float2*)(dO + (((size_t)bh*nq + row+8) << 7) + col) = b;
      }
    }
    if (wd == 0 && gc == 0) {
#pragma unroll
      for (int s = 0; s < 4; s++) {
        int rl = (s>>1)*16 + gr + (s&1)*8;
        dL[(size_t)bh*nq + q0 + wq*32 + rl] = logf(Lr[s]);
      }
    }
  } else {
    size_t pb = (size_t)(sp*BH_ + bh)*320 + q0;
#pragma unroll
    for (int m = 0; m < 2; m++) {
      int rl = wq*32 + m*16 + gr;
#pragma unroll
      for (int n = 0; n < 4; n++) {
        int col = wd*32 + n*8 + 2*gc;
        *(float2*)(g_part_o + ((pb + rl)   << 7) + col) = make_float2(oacc[m][n][0], oacc[m][n][1]);
        *(float2*)(g_part_o + ((pb + rl+8) << 7) + col) = make_float2(oacc[m][n][2], oacc[m][n][3]);
      }
    }
    if (wd == 0 && gc == 0) {
#pragma unroll
      for (int s = 0; s < 4; s++) {
        int rl = (s>>1)*16 + gr + (s&1)*8;
        g_part_l[pb + wq*32 + rl] = Lr[s];
      }
    }
  }
}

// ---------------- p2 merge ----------------
__global__ void __launch_bounds__(256) merge3_kernel() {
  int bh = blockIdx.y;
  int w = threadIdx.x >> 5, lane = threadIdx.x & 31;
  int row = blockIdx.x*8 + w;
  if (row >= S_) return;
  float L = 0.f;
  float4 o = make_float4(0,0,0,0);
#pragma unroll
  for (int s = 0; s < 8; s++) {
    size_t ri = (size_t)(s*BH_ + bh)*320 + row;
    L += g_part_l[ri];
    float4 po = *(const float4*)(g_part_o + (ri << 7) + lane*4);
    o.x += po.x; o.y += po.y; o.z += po.z; o.w += po.w;
  }
  float inv = 1.0f / L;
  o.x*=inv; o.y*=inv; o.z*=inv; o.w*=inv;
  *(float4*)(g_a2 + (((size_t)bh*S_ + row) << 7) + lane*4) = o;
  if (lane == 0) g_l2[(size_t)bh*S_ + row] = logf(L);
}

// ---------------- p1 combine + broadcast ----------------
__global__ void __launch_bounds__(256) combine_kernel(float* __restrict__ out, int has_lse) {
  unsigned wi = (blockIdx.x * 256u + threadIdx.x) >> 5;
  int lane = threadIdx.x & 31;
  int bh = wi >> 10, j = wi & 1023;
  float l1 = g_lse1[wi] + LN8_F;
  float ld = g_ldel[wi];
  float la = g_ladd[wi];
  float c1 = expf(ld - l1);
  float inv1 = 1.0f / (1.0f - c1);
  float lp1 = l1 + log1pf(-c1);
  float c2 = 1.0f / (1.0f + expf(la - lp1));
  float lse = fmaxf(lp1, la) + log1pf(expf(-fabsf(lp1 - la)));
  size_t off = ((size_t)wi << 7) + lane*4;
  float4 a0 = *(const float4*)(g_attn1 + off);
  float4 ad = *(const float4*)(g_adel + off);
  float4 aa = *(const float4*)(g_aadd + off);
  float4 r;
  float c2b = 1.0f - c2;
  r.x = c2*((a0.x - c1*ad.x)*inv1) + c2b*aa.x;
  r.y = c2*((a0.y - c1*ad.y)*inv1) + c2b*aa.y;
  r.z = c2*((a0.z - c1*ad.z)*inv1) + c2b*aa.z;
  r.w = c2*((a0.w - c1*ad.w)*inv1) + c2b*aa.w;
  float* outl = out + (size_t)BH_*NTOK*D_;
#pragma unroll
  for (int g = 0; g < G_; g++) {
    size_t orow = (size_t)bh*NTOK + g*P_ + j;
    *(float4*)(out + (orow << 7) + lane*4) = r;
    if (lane == 0 && has_lse) outl[orow] = lse;
  }
}

// ---------------- p2 scatter ----------------
__global__ void __launch_bounds__(256) scatter_kernel(float* __restrict__ out, int has_lse) {
  unsigned wi = (blockIdx.x * 256u + threadIdx.x) >> 5;
  int lane = threadIdx.x & 31;
  if (wi >= (unsigned)(BH_*S_)) return;
  int bh = wi / S_;
  int rr = wi % S_;
  int g = rr / MK_, tt = rr % MK_;
  int qj = g_qidx[(bh*G_+g)*MK_+tt];
  size_t orow = (size_t)bh*NTOK + g*P_ + qj;
  float4 a = *(const float4*)(g_a2 + ((size_t)wi << 7) + lane*4);
  *(float4*)(out + (orow << 7) + lane*4) = a;
  if (lane == 0 && has_lse) out[(size_t)BH_*NTOK*D_ + orow] = g_l2[wi];
}

// ---------------- launch ----------------
extern "C" void kernel_launch(void* const* d_in, const int* in_sizes, int n_in,
                              void* d_out, int out_size) {
  const float* q = (const float*)d_in[0];
  const float* k = (const float*)d_in[1];
  const float* v = (const float*)d_in[2];
  float* out = (float*)d_out;
  int has_lse = (out_size >= BH_*NTOK*(D_ + 1)) ? 1 : 0;

  cudaFuncSetAttribute(attn_bf16_kernel,
                       cudaFuncAttributeMaxDynamicSharedMemorySize, SMEM_B);

  means_kernel <<<(BH_*P_*32)/256, 256>>>(q, k, v);
  scores_kernel<<<(2*BH_*G_*P_*32)/256, 256>>>(q, k);
  topk_kernel  <<<dim3(BH_*G_, 2), 256>>>();
  gather_kernel<<<(BH_*S_*32 + 255)/256, 256>>>(q, k, v);

  attn_bf16_kernel<<<2816, 256, SMEM_B>>>(k, v);
  merge3_kernel <<<dim3((S_+7)/8, BH_), 256>>>();

  combine_kernel<<<(BH_*P_*32)/256, 256>>>(out, has_lse);
  scatter_kernel<<<(BH_*S_*32 + 255)/256, 256>>>(out, has_lse);
}

// round 10
// speedup vs baseline: 5.0627x; 1.2259x over previous
#include <cuda_runtime.h>
#include <cuda_bf16.h>
#include <stdint.h>
#include <math.h>

#define B_    2
#define H_    16
#define NTOK  8192
#define D_    128
#define G_    8
#define P_    1024
#define MK_   34
#define S_    (G_*MK_)
#define BH_   (B_*H_)

#define SCALE_F 0.08838834764831843f
#define LN8_F   2.0794415416798357f
#define TINY_F  1.17549435e-38f
#define EPS_F   1.1920929e-07f

// smem u32 offsets (red aliased over PH after last PV)
#define U_QH 0
#define U_QL 4096
#define U_KH 8192
#define U_KL 12288
#define U_VH 16384
#define U_VL 20480
#define U_PH 24576
#define U_PL 26624
#define SMEM_U 28672
#define SMEM_B (SMEM_U*4)

__device__ __align__(16) float g_qrep [BH_*P_*D_];
__device__ __align__(16) float g_krep [BH_*P_*D_];
__device__ __align__(16) float g_vmean[BH_*P_*D_];
__device__ __align__(16) float g_attn1[BH_*P_*D_];
__device__ __align__(16) float g_adel [BH_*P_*D_];
__device__ __align__(16) float g_aadd [BH_*P_*D_];
__device__ float g_lse1[BH_*P_];
__device__ float g_ldel[BH_*P_];
__device__ float g_ladd[BH_*P_];
__device__ float g_score_k[BH_*G_*P_];
__device__ float g_score_q[BH_*G_*P_];
__device__ int   g_kidx[BH_*G_*MK_];
__device__ int   g_qidx[BH_*G_*MK_];
__device__ __align__(16) float g_ksub   [BH_*S_*D_];
__device__ __align__(16) float g_krepsub[BH_*S_*D_];
__device__ __align__(16) float g_vsub   [BH_*S_*D_];
__device__ __align__(16) float g_qsub   [BH_*S_*D_];
__device__ __align__(16) float g_a2     [BH_*S_*D_];
__device__ float g_l2[BH_*S_];
__device__ __align__(16) float g_part_o[(size_t)8*BH_*320*D_];
__device__ float g_part_l[8*BH_*320];

__device__ __forceinline__ void split2(float x0, float x1, uint32_t& hp, uint32_t& lp) {
  __nv_bfloat162 h = __floats2bfloat162_rn(x0, x1);
  hp = *reinterpret_cast<uint32_t*>(&h);
  float h0 = __uint_as_float(hp << 16);
  float h1 = __uint_as_float(hp & 0xffff0000u);
  __nv_bfloat162 l = __floats2bfloat162_rn(x0 - h0, x1 - h1);
  lp = *reinterpret_cast<uint32_t*>(&l);
}

#define MMAB(d,a,b0,b1) \
  asm volatile("mma.sync.aligned.m16n8k16.row.col.f32.bf16.bf16.f32 " \
  "{%0,%1,%2,%3},{%4,%5,%6,%7},{%8,%9},{%0,%1,%2,%3};" \
  : "+f"((d)[0]),"+f"((d)[1]),"+f"((d)[2]),"+f"((d)[3]) \
  : "r"((a)[0]),"r"((a)[1]),"r"((a)[2]),"r"((a)[3]),"r"(b0),"r"(b1))

// ---------------- threefry2x32 ----------------
__device__ __forceinline__ void threefry2x32(uint32_t k0, uint32_t k1,
                                             uint32_t x0, uint32_t x1,
                                             uint32_t& o0, uint32_t& o1) {
  uint32_t k2 = k0 ^ k1 ^ 0x1BD11BDAu;
  x0 += k0; x1 += k1;
#define TFR(r) { x0 += x1; x1 = (x1 << (r)) | (x1 >> (32 - (r))); x1 ^= x0; }
  TFR(13) TFR(15) TFR(26) TFR(6)   x0 += k1; x1 += k2 + 1u;
  TFR(17) TFR(29) TFR(16) TFR(24)  x0 += k2; x1 += k0 + 2u;
  TFR(13) TFR(15) TFR(26) TFR(6)   x0 += k0; x1 += k1 + 3u;
  TFR(17) TFR(29) TFR(16) TFR(24)  x0 += k1; x1 += k2 + 4u;
  TFR(13) TFR(15) TFR(26) TFR(6)   x0 += k2; x1 += k0 + 5u;
#undef TFR
  o0 = x0; o1 = x1;
}

// ---------------- fused means + residual-norm + gumbel scores ----------------
// warp per (bh, j): 8 group rows in regs; mean -> rep; residual ss per g; RNG on 16 lanes
__global__ void __launch_bounds__(256) prep_kernel(const float* __restrict__ q,
                                                   const float* __restrict__ k,
                                                   const float* __restrict__ v) {
  int wid = (blockIdx.x*256 + threadIdx.x) >> 5;   // 0..32767
  int lane = threadIdx.x & 31;
  int bh = wid >> 10, j = wid & 1023;
  size_t base = (((size_t)bh*NTOK) << 7) + (((size_t)j) << 7) + lane*4;
  size_t rbase = ((((size_t)bh*P_) + j) << 7) + lane*4;
  float4 rows[8];
  float kss = 0.f, qss = 0.f;

  // K
  float4 mn = make_float4(0,0,0,0);
#pragma unroll
  for (int g = 0; g < 8; g++) {
    rows[g] = *(const float4*)(k + base + ((size_t)g*P_ << 7));
    mn.x+=rows[g].x; mn.y+=rows[g].y; mn.z+=rows[g].z; mn.w+=rows[g].w;
  }
  mn.x*=0.125f; mn.y*=0.125f; mn.z*=0.125f; mn.w*=0.125f;
  *(float4*)(g_krep + rbase) = mn;
#pragma unroll
  for (int g = 0; g < 8; g++) {
    float dx=rows[g].x-mn.x, dy=rows[g].y-mn.y, dz=rows[g].z-mn.z, dw=rows[g].w-mn.w;
    float ss = dx*dx + dy*dy + dz*dz + dw*dw;
#pragma unroll
    for (int off = 16; off; off >>= 1) ss += __shfl_xor_sync(0xffffffffu, ss, off);
    if (lane == g) kss = ss;
  }
  // Q
  mn = make_float4(0,0,0,0);
#pragma unroll
  for (int g = 0; g < 8; g++) {
    rows[g] = *(const float4*)(q + base + ((size_t)g*P_ << 7));
    mn.x+=rows[g].x; mn.y+=rows[g].y; mn.z+=rows[g].z; mn.w+=rows[g].w;
  }
  mn.x*=0.125f; mn.y*=0.125f; mn.z*=0.125f; mn.w*=0.125f;
  *(float4*)(g_qrep + rbase) = mn;
#pragma unroll
  for (int g = 0; g < 8; g++) {
    float dx=rows[g].x-mn.x, dy=rows[g].y-mn.y, dz=rows[g].z-mn.z, dw=rows[g].w-mn.w;
    float ss = dx*dx + dy*dy + dz*dz + dw*dw;
#pragma unroll
    for (int off = 16; off; off >>= 1) ss += __shfl_xor_sync(0xffffffffu, ss, off);
    if (lane == 8 + g) qss = ss;
  }
  // V mean
  mn = make_float4(0,0,0,0);
#pragma unroll
  for (int g = 0; g < 8; g++) {
    float4 r = *(const float4*)(v + base + ((size_t)g*P_ << 7));
    mn.x+=r.x; mn.y+=r.y; mn.z+=r.z; mn.w+=r.w;
  }
  mn.x*=0.125f; mn.y*=0.125f; mn.z*=0.125f; mn.w*=0.125f;
  *(float4*)(g_vmean + rbase) = mn;

  // RNG + score on lanes 0..15 (t = lane>>3, g = lane&7)
  if (lane < 16) {
    int t = lane >> 3, g = lane & 7;
    float ss = t ? qss : kss;
    unsigned r = (unsigned)(bh*8192 + g*1024 + j);
    uint32_t rk0, rk1, o0, o1;
    threefry2x32(0u, 42u, 0u, (uint32_t)t, rk0, rk1);
    threefry2x32(rk0, rk1, 0u, r, o0, o1);
    uint32_t bits = o0 ^ o1;
    float u = __uint_as_float((bits >> 9) | 0x3f800000u) - 1.0f;
    if (u <= 0.0f) u = TINY_F;
    float gum = -logf(-logf(u));
    float score = logf(sqrtf(ss) * 100.0f + EPS_F) + gum;
    (t ? g_score_q : g_score_k)[r] = score;
  }
}

// ---------------- top-34 ----------------
__global__ void __launch_bounds__(256) topk_kernel() {
  int grp = blockIdx.x;
  int t   = blockIdx.y;
  float* sc = (t ? g_score_q : g_score_k) + (size_t)grp * P_;
  int*  out = (t ? g_qidx    : g_kidx   ) + (size_t)grp * MK_;
  __shared__ float sv[1024];
  __shared__ float rv[256];
  __shared__ int   ri[256];
  int tid = threadIdx.x;
#pragma unroll
  for (int r = 0; r < 4; r++) sv[tid + 256*r] = sc[tid + 256*r];
  __syncthreads();
  for (int it = 0; it < MK_; it++) {
    float bv = -INFINITY; int bi = 0x7fffffff;
#pragma unroll
    for (int r = 0; r < 4; r++) {
      int i = tid + 256*r;
      float vv = sv[i];
      if (vv > bv || (vv == bv && i < bi)) { bv = vv; bi = i; }
    }
    rv[tid] = bv; ri[tid] = bi;
    __syncthreads();
    for (int s = 128; s; s >>= 1) {
      if (tid < s) {
        float vv = rv[tid+s]; int i2 = ri[tid+s];
        if (vv > rv[tid] || (vv == rv[tid] && i2 < ri[tid])) { rv[tid]=vv; ri[tid]=i2; }
      }
      __syncthreads();
    }
    if (tid == 0) { out[it] = ri[0]; sv[ri[0]] = -INFINITY; }
    __syncthreads();
  }
}

// ---------------- gathers ----------------
__global__ void __launch_bounds__(256) gather_kernel(const float* __restrict__ q,
                                                     const float* __restrict__ k,
                                                     const float* __restrict__ v) {
  unsigned wi = (blockIdx.x * 256u + threadIdx.x) >> 5;
  int lane = threadIdx.x & 31;
  if (wi >= (unsigned)(BH_*S_)) return;
  int bh = wi / S_;
  int rr = wi % S_;
  int g = rr / MK_, tt = rr % MK_;
  int kj = g_kidx[(bh*G_+g)*MK_+tt];
  int qj = g_qidx[(bh*G_+g)*MK_+tt];
  size_t srck = ((size_t)bh*NTOK + g*P_ + kj) << 7;
  size_t srcq = ((size_t)bh*NTOK + g*P_ + qj) << 7;
  size_t dst  = ((size_t)wi << 7) + lane*4;
  *(float4*)(g_ksub    + dst) = *(const float4*)(k + srck + lane*4);
  *(float4*)(g_vsub    + dst) = *(const float4*)(v + srck + lane*4);
  *(float4*)(g_krepsub + dst) = *(const float4*)(g_krep + (((size_t)bh*P_ + kj) << 7) + lane*4);
  *(float4*)(g_qsub    + dst) = *(const float4*)(q + srcq + lane*4);
}

// ---------------- unified bf16x3 mma flash attention (bh-major blocks) ----------------
// per bh: j in [0,40) p2 (sp=j/5, qb=j%5); [40,56) p0; [56,72) p1-del; [72,88) p1-add
__global__ void __launch_bounds__(256, 2)
attn_bf16_kernel(const float* __restrict__ kin, const float* __restrict__ vin) {
  extern __shared__ uint32_t su[];
  uint32_t* Qh = su + U_QH; uint32_t* Ql = su + U_QL;
  uint32_t* Kh = su + U_KH; uint32_t* Kl = su + U_KL;
  uint32_t* Vth = su + U_VH; uint32_t* Vtl = su + U_VL;
  uint32_t* Php = su + U_PH; uint32_t* Plp = su + U_PL;
  float* red = (float*)(su + U_PH);   // aliased; used only after last PV

  int tid = threadIdx.x;
  int w = tid >> 5, lane = tid & 31;
  int gr = lane >> 2, gc = lane & 3;
  int wq = w & 1, wd = w >> 1;

  int bh = blockIdx.x / 88;
  int j  = blockIdx.x % 88;
  int mode, qb, sp = 0;
  if (j < 40) { mode = 3; sp = j / 5; qb = j % 5; }
  else { mode = (j - 40) >> 4; qb = (j - 40) & 15; }

  const float *Qs, *Ks, *Vs; float *dO, *dL;
  int nq, ke, ntile, k0;
  if (mode == 0) { Qs=g_qrep+(size_t)bh*P_*D_; Ks=g_krep+(size_t)bh*P_*D_;  Vs=g_vmean+(size_t)bh*P_*D_;
                   nq=P_; ke=P_; ntile=16; k0=0; dO=g_attn1; dL=g_lse1; }
  else if (mode==1){Qs=g_qrep+(size_t)bh*P_*D_; Ks=g_krepsub+(size_t)bh*S_*D_; Vs=g_vsub+(size_t)bh*S_*D_;
                   nq=P_; ke=S_; ntile=5; k0=0; dO=g_adel; dL=g_ldel; }
  else if (mode==2){Qs=g_qrep+(size_t)bh*P_*D_; Ks=g_ksub+(size_t)bh*S_*D_;  Vs=g_vsub+(size_t)bh*S_*D_;
                   nq=P_; ke=S_; ntile=5; k0=0; dO=g_aadd; dL=g_ladd; }
  else           { Qs=g_qsub+(size_t)bh*S_*D_; Ks=kin+(size_t)bh*NTOK*D_;   Vs=vin+(size_t)bh*NTOK*D_;
                   nq=S_; k0=sp*1024; ke=k0+1024; ntile=16; dO=0; dL=0; }
  int q0 = qb * 64;

  // ---- stage Q hi/lo ----
#pragma unroll
  for (int t = 0; t < 8; t++) {
    int lin = tid + t*256;
    int row = lin >> 5, c4 = lin & 31;
    int gq = q0 + row; if (gq > nq-1) gq = nq-1;
    float4 v = *(const float4*)(Qs + ((size_t)gq << 7) + c4*4);
    v.x*=SCALE_F; v.y*=SCALE_F; v.z*=SCALE_F; v.w*=SCALE_F;
    uint32_t hp0,lp0,hp1,lp1;
    split2(v.x, v.y, hp0, lp0);
    split2(v.z, v.w, hp1, lp1);
    int r7 = row & 7;
    int j0 = 2*c4, j1 = j0+1;
    int col0 = (((j0>>3) ^ r7)<<3) + ((j0&3)<<1) + ((j0>>2)&1);
    int col1 = (((j1>>3) ^ r7)<<3) + ((j1&3)<<1) + ((j1>>2)&1);
    Qh[row*64+col0]=hp0; Ql[row*64+col0]=lp0;
    Qh[row*64+col1]=hp1; Ql[row*64+col1]=lp1;
  }

  float oacc[2][4][4];
#pragma unroll
  for (int m=0;m<2;m++)
#pragma unroll
    for (int n=0;n<4;n++)
#pragma unroll
      for (int t=0;t<4;t++) oacc[m][n][t]=0.f;
  float psum[4] = {0.f,0.f,0.f,0.f};

  int r0 = wq*32 + gr;
  int n0 = wd*16 + gr;
  int cx3 = gr & 3;

  for (int tile = 0; tile < ntile; tile++) {
    int kb = k0 + tile*64;
    __syncthreads();
#pragma unroll
    for (int t = 0; t < 8; t++) {
      int lin = tid + t*256;
      int row = lin >> 5, c4 = lin & 31;
      int gk = kb + row;
      float4 v = make_float4(0,0,0,0);
      if (gk < ke) v = *(const float4*)(Ks + ((size_t)gk << 7) + c4*4);
      uint32_t hp0,lp0,hp1,lp1;
      split2(v.x, v.y, hp0, lp0);
      split2(v.z, v.w, hp1, lp1);
      int r7 = row & 7;
      int j0 = 2*c4, j1 = j0+1;
      int col0 = (((j0>>3) ^ r7)<<3) + ((j0&3)<<1) + ((j0>>2)&1);
      int col1 = (((j1>>3) ^ r7)<<3) + ((j1&3)<<1) + ((j1>>2)&1);
      Kh[row*64+col0]=hp0; Kl[row*64+col0]=lp0;
      Kh[row*64+col1]=hp1; Kl[row*64+col1]=lp1;
    }
#pragma unroll
    for (int t = 0; t < 4; t++) {
      int lin = tid + t*256;
      int kp = lin & 31, dg = lin >> 5;
      int d0 = dg*4;
      int ka = kb + 2*kp;
      float4 va = make_float4(0,0,0,0), vb = va;
      if (ka   < ke) va = *(const float4*)(Vs + ((size_t)ka << 7) + d0);
      if (ka+1 < ke) vb = *(const float4*)(Vs + ((size_t)(ka+1) << 7) + d0);
      int cc = kp>>3, gg = kp&3, hh = (kp>>2)&1;
      uint32_t hp, lp;
      split2(va.x, vb.x, hp, lp);
      Vth[(d0+0)*32 + (((cc^0)<<3)+(gg<<1)+hh)] = hp; Vtl[(d0+0)*32 + (((cc^0)<<3)+(gg<<1)+hh)] = lp;
      split2(va.y, vb.y, hp, lp);
      Vth[(d0+1)*32 + (((cc^1)<<3)+(gg<<1)+hh)] = hp; Vtl[(d0+1)*32 + (((cc^1)<<3)+(gg<<1)+hh)] = lp;
      split2(va.z, vb.z, hp, lp);
      Vth[(d0+2)*32 + (((cc^2)<<3)+(gg<<1)+hh)] = hp; Vtl[(d0+2)*32 + (((cc^2)<<3)+(gg<<1)+hh)] = lp;
      split2(va.w, vb.w, hp, lp);
      Vth[(d0+3)*32 + (((cc^3)<<3)+(gg<<1)+hh)] = hp; Vtl[(d0+3)*32 + (((cc^3)<<3)+(gg<<1)+hh)] = lp;
    }
    __syncthreads();

    // S = Q K^T (3-pass)
    float sacc[2][2][4];
#pragma unroll
    for (int m=0;m<2;m++)
#pragma unroll
      for (int n=0;n<2;n++)
#pragma unroll
        for (int t=0;t<4;t++) sacc[m][n][t]=0.f;
#pragma unroll
    for (int c = 0; c < 8; c++) {
      int cq = ((c ^ gr) << 3) + (gc << 1);
      uint2 aH[2][2], aL[2][2];
      aH[0][0] = *(const uint2*)(Qh + (r0   )*64 + cq);
      aH[0][1] = *(const uint2*)(Qh + (r0+8 )*64 + cq);
      aH[1][0] = *(const uint2*)(Qh + (r0+16)*64 + cq);
      aH[1][1] = *(const uint2*)(Qh + (r0+24)*64 + cq);
      aL[0][0] = *(const uint2*)(Ql + (r0   )*64 + cq);
      aL[0][1] = *(const uint2*)(Ql + (r0+8 )*64 + cq);
      aL[1][0] = *(const uint2*)(Ql + (r0+16)*64 + cq);
      aL[1][1] = *(const uint2*)(Ql + (r0+24)*64 + cq);
      uint2 bH[2], bL[2];
      bH[0] = *(const uint2*)(Kh + (n0  )*64 + cq);
      bH[1] = *(const uint2*)(Kh + (n0+8)*64 + cq);
      bL[0] = *(const uint2*)(Kl + (n0  )*64 + cq);
      bL[1] = *(const uint2*)(Kl + (n0+8)*64 + cq);
#pragma unroll
      for (int m = 0; m < 2; m++) {
        uint32_t Ah[4] = {aH[m][0].x, aH[m][1].x, aH[m][0].y, aH[m][1].y};
        uint32_t Al[4] = {aL[m][0].x, aL[m][1].x, aL[m][0].y, aL[m][1].y};
#pragma unroll
        for (int n = 0; n < 2; n++) {
          MMAB(sacc[m][n], Ah, bH[n].x, bH[n].y);
          MMAB(sacc[m][n], Ah, bL[n].x, bL[n].y);
          MMAB(sacc[m][n], Al, bH[n].x, bH[n].y);
        }
      }
    }
    // exp + psum + store P hi/lo
#pragma unroll
    for (int m = 0; m < 2; m++) {
      int rm = wq*32 + m*16 + gr;
#pragma unroll
      for (int n = 0; n < 2; n++) {
        int colb = wd*16 + n*8 + 2*gc;
        int gcol = kb + colb;
        float p0 = (gcol   < ke) ? __expf(sacc[m][n][0]) : 0.f;
        float p1 = (gcol+1 < ke) ? __expf(sacc[m][n][1]) : 0.f;
        float p2 = (gcol   < ke) ? __expf(sacc[m][n][2]) : 0.f;
        float p3 = (gcol+1 < ke) ? __expf(sacc[m][n][3]) : 0.f;
        psum[m*2]   += p0 + p1;
        psum[m*2+1] += p2 + p3;
        int colp = ((wd ^ cx3)<<3) + (gc<<1) + n;
        uint32_t hp, lp;
        split2(p0, p1, hp, lp);
        Php[rm*32 + colp] = hp; Plp[rm*32 + colp] = lp;
        split2(p2, p3, hp, lp);
        Php[(rm+8)*32 + colp] = hp; Plp[(rm+8)*32 + colp] = lp;
      }
    }
    __syncthreads();
    // O += P V (3-pass)
#pragma unroll
    for (int c = 0; c < 4; c++) {
      int cp = (((c ^ cx3) & 3) << 3) + (gc << 1);
      uint2 pH[2][2], pL[2][2];
      pH[0][0] = *(const uint2*)(Php + (r0   )*32 + cp);
      pH[0][1] = *(const uint2*)(Php + (r0+8 )*32 + cp);
      pH[1][0] = *(const uint2*)(Php + (r0+16)*32 + cp);
      pH[1][1] = *(const uint2*)(Php + (r0+24)*32 + cp);
      pL[0][0] = *(const uint2*)(Plp + (r0   )*32 + cp);
      pL[0][1] = *(const uint2*)(Plp + (r0+8 )*32 + cp);
      pL[1][0] = *(const uint2*)(Plp + (r0+16)*32 + cp);
      pL[1][1] = *(const uint2*)(Plp + (r0+24)*32 + cp);
      uint2 vH[4], vL[4];
      int dnb = wd*32 + gr;
#pragma unroll
      for (int n = 0; n < 4; n++) {
        vH[n] = *(const uint2*)(Vth + (dnb + n*8)*32 + cp);
        vL[n] = *(const uint2*)(Vtl + (dnb + n*8)*32 + cp);
      }
#pragma unroll
      for (int m = 0; m < 2; m++) {
        uint32_t Ph4[4] = {pH[m][0].x, pH[m][1].x, pH[m][0].y, pH[m][1].y};
        uint32_t Pl4[4] = {pL[m][0].x, pL[m][1].x, pL[m][0].y, pL[m][1].y};
#pragma unroll
        for (int n = 0; n < 4; n++) {
          MMAB(oacc[m][n], Ph4, vH[n].x, vH[n].y);
          MMAB(oacc[m][n], Ph4, vL[n].x, vL[n].y);
          MMAB(oacc[m][n], Pl4, vH[n].x, vH[n].y);
        }
      }
    }
  }

  // psum reduce + epilogue
#pragma unroll
  for (int s = 0; s < 4; s++) {
    psum[s] += __shfl_xor_sync(0xffffffffu, psum[s], 1);
    psum[s] += __shfl_xor_sync(0xffffffffu, psum[s], 2);
  }
  __syncthreads();
  if (gc == 0) {
#pragma unroll
    for (int s = 0; s < 4; s++) {
      int rl = (s>>1)*16 + gr + (s&1)*8;
      red[(wq*4 + wd)*32 + rl] = psum[s];
    }
  }
  __syncthreads();
  float Lr[4], iv[4];
#pragma unroll
  for (int s = 0; s < 4; s++) {
    int rl = (s>>1)*16 + gr + (s&1)*8;
    float L = red[(wq*4+0)*32+rl] + red[(wq*4+1)*32+rl] +
              red[(wq*4+2)*32+rl] + red[(wq*4+3)*32+rl];
    Lr[s] = L; iv[s] = 1.0f / L;
  }
  if (mode < 3) {
#pragma unroll
    for (int m = 0; m < 2; m++) {
      int row = q0 + wq*32 + m*16 + gr;
#pragma unroll
      for (int n = 0; n < 4; n++) {
        int col = wd*32 + n*8 + 2*gc;
        float2 a = make_float2(oacc[m][n][0]*iv[2*m],   oacc[m][n][1]*iv[2*m]);
        float2 b = make_float2(oacc[m][n][2]*iv[2*m+1], oacc[m][n][3]*iv[2*m+1]);
        *(float2*)(dO + (((size_t)bh*nq + row)   << 7) + col) = a;
        *(float2*)(dO + (((size_t)bh*nq + row+8) << 7) + col) = b;
      }
    }
    if (wd == 0 && gc == 0) {
#pragma unroll
      for (int s = 0; s < 4; s++) {
        int rl = (s>>1)*16 + gr + (s&1)*8;
        dL[(size_t)bh*nq + q0 + wq*32 + rl] = logf(Lr[s]);
      }
    }
  } else {
    size_t pb = (size_t)(sp*BH_ + bh)*320 + q0;
#pragma unroll
    for (int m = 0; m < 2; m++) {
      int rl = wq*32 + m*16 + gr;
#pragma unroll
      for (int n = 0; n < 4; n++) {
        int col = wd*32 + n*8 + 2*gc;
        *(float2*)(g_part_o + ((pb + rl)   << 7) + col) = make_float2(oacc[m][n][0], oacc[m][n][1]);
        *(float2*)(g_part_o + ((pb + rl+8) << 7) + col) = make_float2(oacc[m][n][2], oacc[m][n][3]);
      }
    }
    if (wd == 0 && gc == 0) {
#pragma unroll
      for (int s = 0; s < 4; s++) {
        int rl = (s>>1)*16 + gr + (s&1)*8;
        g_part_l[pb + wq*32 + rl] = Lr[s];
      }
    }
  }
}

// ---------------- p2 merge ----------------
__global__ void __launch_bounds__(256) merge3_kernel() {
  int bh = blockIdx.y;
  int w = threadIdx.x >> 5, lane = threadIdx.x & 31;
  int row = blockIdx.x*8 + w;
  if (row >= S_) return;
  float L = 0.f;
  float4 o = make_float4(0,0,0,0);
#pragma unroll
  for (int s = 0; s < 8; s++) {
    size_t ri = (size_t)(s*BH_ + bh)*320 + row;
    L += g_part_l[ri];
    float4 po = *(const float4*)(g_part_o + (ri << 7) + lane*4);
    o.x += po.x; o.y += po.y; o.z += po.z; o.w += po.w;
  }
  float inv = 1.0f / L;
  o.x*=inv; o.y*=inv; o.z*=inv; o.w*=inv;
  *(float4*)(g_a2 + (((size_t)bh*S_ + row) << 7) + lane*4) = o;
  if (lane == 0) g_l2[(size_t)bh*S_ + row] = logf(L);
}

// ---------------- p1 combine + broadcast ----------------
__global__ void __launch_bounds__(256) combine_kernel(float* __restrict__ out, int has_lse) {
  unsigned wi = (blockIdx.x * 256u + threadIdx.x) >> 5;
  int lane = threadIdx.x & 31;
  int bh = wi >> 10, j = wi & 1023;
  float l1 = g_lse1[wi] + LN8_F;
  float ld = g_ldel[wi];
  float la = g_ladd[wi];
  float c1 = expf(ld - l1);
  float inv1 = 1.0f / (1.0f - c1);
  float lp1 = l1 + log1pf(-c1);
  float c2 = 1.0f / (1.0f + expf(la - lp1));
  float lse = fmaxf(lp1, la) + log1pf(expf(-fabsf(lp1 - la)));
  size_t off = ((size_t)wi << 7) + lane*4;
  float4 a0 = *(const float4*)(g_attn1 + off);
  float4 ad = *(const float4*)(g_adel + off);
  float4 aa = *(const float4*)(g_aadd + off);
  float4 r;
  float c2b = 1.0f - c2;
  r.x = c2*((a0.x - c1*ad.x)*inv1) + c2b*aa.x;
  r.y = c2*((a0.y - c1*ad.y)*inv1) + c2b*aa.y;
  r.z = c2*((a0.z - c1*ad.z)*inv1) + c2b*aa.z;
  r.w = c2*((a0.w - c1*ad.w)*inv1) + c2b*aa.w;
  float* outl = out + (size_t)BH_*NTOK*D_;
#pragma unroll
  for (int g = 0; g < G_; g++) {
    size_t orow = (size_t)bh*NTOK + g*P_ + j;
    *(float4*)(out + (orow << 7) + lane*4) = r;
    if (lane == 0 && has_lse) outl[orow] = lse;
  }
}

// ---------------- p2 scatter ----------------
__global__ void __launch_bounds__(256) scatter_kernel(float* __restrict__ out, int has_lse) {
  unsigned wi = (blockIdx.x * 256u + threadIdx.x) >> 5;
  int lane = threadIdx.x & 31;
  if (wi >= (unsigned)(BH_*S_)) return;
  int bh = wi / S_;
  int rr = wi % S_;
  int g = rr / MK_, tt = rr % MK_;
  int qj = g_qidx[(bh*G_+g)*MK_+tt];
  size_t orow = (size_t)bh*NTOK + g*P_ + qj;
  float4 a = *(const float4*)(g_a2 + ((size_t)wi << 7) + lane*4);
  *(float4*)(out + (orow << 7) + lane*4) = a;
  if (lane == 0 && has_lse) out[(size_t)BH_*NTOK*D_ + orow] = g_l2[wi];
}

// ---------------- launch ----------------
extern "C" void kernel_launch(void* const* d_in, const int* in_sizes, int n_in,
                              void* d_out, int out_size) {
  const float* q = (const float*)d_in[0];
  const float* k = (const float*)d_in[1];
  const float* v = (const float*)d_in[2];
  float* out = (float*)d_out;
  int has_lse = (out_size >= BH_*NTOK*(D_ + 1)) ? 1 : 0;

  cudaFuncSetAttribute(attn_bf16_kernel,
                       cudaFuncAttributeMaxDynamicSharedMemorySize, SMEM_B);

  prep_kernel  <<<4096, 256>>>(q, k, v);
  topk_kernel  <<<dim3(BH_*G_, 2), 256>>>();
  gather_kernel<<<(BH_*S_*32 + 255)/256, 256>>>(q, k, v);

  attn_bf16_kernel<<<2816, 256, SMEM_B>>>(k, v);
  merge3_kernel <<<dim3((S_+7)/8, BH_), 256>>>();

  combine_kernel<<<(BH_*P_*32)/256, 256>>>(out, has_lse);
  scatter_kernel<<<(BH_*S_*32 + 255)/256, 256>>>(out, has_lse);
}

// round 12
// speedup vs baseline: 5.6807x; 1.1221x over previous
#include <cuda_runtime.h>
#include <cuda_bf16.h>
#include <stdint.h>
#include <math.h>

#define B_    2
#define H_    16
#define NTOK  8192
#define D_    128
#define G_    8
#define P_    1024
#define MK_   34
#define S_    (G_*MK_)
#define BH_   (B_*H_)

#define SCALE_F 0.08838834764831843f
#define LN8_F   2.0794415416798357f
#define TINY_F  1.17549435e-38f
#define EPS_F   1.1920929e-07f

// smem u32 offsets (no P buffers; OX/red alias dead regions at epilogue)
#define U_QH 0
#define U_QL 4096
#define U_KH 8192
#define U_KL 12288
#define U_VH 16384
#define U_VL 20480
#define SMEM_U 24576
#define SMEM_B (SMEM_U*4)

__device__ __align__(16) float g_qrep [BH_*P_*D_];
__device__ __align__(16) float g_krep [BH_*P_*D_];
__device__ __align__(16) float g_vmean[BH_*P_*D_];
__device__ __align__(16) float g_attn1[BH_*P_*D_];
__device__ __align__(16) float g_adel [BH_*P_*D_];
__device__ __align__(16) float g_aadd [BH_*P_*D_];
__device__ float g_lse1[BH_*P_];
__device__ float g_ldel[BH_*P_];
__device__ float g_ladd[BH_*P_];
__device__ float g_score_k[BH_*G_*P_];
__device__ float g_score_q[BH_*G_*P_];
__device__ int   g_kidx[BH_*G_*MK_];
__device__ int   g_qidx[BH_*G_*MK_];
__device__ __align__(16) float g_ksub   [BH_*S_*D_];
__device__ __align__(16) float g_krepsub[BH_*S_*D_];
__device__ __align__(16) float g_vsub   [BH_*S_*D_];
__device__ __align__(16) float g_qsub   [BH_*S_*D_];
__device__ __align__(16) float g_a2     [BH_*S_*D_];
__device__ float g_l2[BH_*S_];
__device__ __align__(16) float g_part_o[(size_t)8*BH_*320*D_];
__device__ float g_part_l[8*BH_*320];

__device__ __forceinline__ void split2(float x0, float x1, uint32_t& hp, uint32_t& lp) {
  __nv_bfloat162 h = __floats2bfloat162_rn(x0, x1);
  hp = *reinterpret_cast<uint32_t*>(&h);
  float h0 = __uint_as_float(hp << 16);
  float h1 = __uint_as_float(hp & 0xffff0000u);
  __nv_bfloat162 l = __floats2bfloat162_rn(x0 - h0, x1 - h1);
  lp = *reinterpret_cast<uint32_t*>(&l);
}

#define MMAB(d,a,b0,b1) \
  asm volatile("mma.sync.aligned.m16n8k16.row.col.f32.bf16.bf16.f32 " \
  "{%0,%1,%2,%3},{%4,%5,%6,%7},{%8,%9},{%0,%1,%2,%3};" \
  : "+f"((d)[0]),"+f"((d)[1]),"+f"((d)[2]),"+f"((d)[3]) \
  : "r"((a)[0]),"r"((a)[1]),"r"((a)[2]),"r"((a)[3]),"r"(b0),"r"(b1))

// ---------------- threefry2x32 ----------------
__device__ __forceinline__ void threefry2x32(uint32_t k0, uint32_t k1,
                                             uint32_t x0, uint32_t x1,
                                             uint32_t& o0, uint32_t& o1) {
  uint32_t k2 = k0 ^ k1 ^ 0x1BD11BDAu;
  x0 += k0; x1 += k1;
#define TFR(r) { x0 += x1; x1 = (x1 << (r)) | (x1 >> (32 - (r))); x1 ^= x0; }
  TFR(13) TFR(15) TFR(26) TFR(6)   x0 += k1; x1 += k2 + 1u;
  TFR(17) TFR(29) TFR(16) TFR(24)  x0 += k2; x1 += k0 + 2u;
  TFR(13) TFR(15) TFR(26) TFR(6)   x0 += k0; x1 += k1 + 3u;
  TFR(17) TFR(29) TFR(16) TFR(24)  x0 += k1; x1 += k2 + 4u;
  TFR(13) TFR(15) TFR(26) TFR(6)   x0 += k2; x1 += k0 + 5u;
#undef TFR
  o0 = x0; o1 = x1;
}

// ---------------- fused means + scores ----------------
__global__ void __launch_bounds__(256) prep_kernel(const float* __restrict__ q,
                                                   const float* __restrict__ k,
                                                   const float* __restrict__ v) {
  int wid = (blockIdx.x*256 + threadIdx.x) >> 5;
  int lane = threadIdx.x & 31;
  int bh = wid >> 10, j = wid & 1023;
  size_t base = (((size_t)bh*NTOK) << 7) + (((size_t)j) << 7) + lane*4;
  size_t rbase = ((((size_t)bh*P_) + j) << 7) + lane*4;
  float4 rows[8];
  float kss = 0.f, qss = 0.f;

  float4 mn = make_float4(0,0,0,0);
#pragma unroll
  for (int g = 0; g < 8; g++) {
    rows[g] = *(const float4*)(k + base + ((size_t)g*P_ << 7));
    mn.x+=rows[g].x; mn.y+=rows[g].y; mn.z+=rows[g].z; mn.w+=rows[g].w;
  }
  mn.x*=0.125f; mn.y*=0.125f; mn.z*=0.125f; mn.w*=0.125f;
  *(float4*)(g_krep + rbase) = mn;
#pragma unroll
  for (int g = 0; g < 8; g++) {
    float dx=rows[g].x-mn.x, dy=rows[g].y-mn.y, dz=rows[g].z-mn.z, dw=rows[g].w-mn.w;
    float ss = dx*dx + dy*dy + dz*dz + dw*dw;
#pragma unroll
    for (int off = 16; off; off >>= 1) ss += __shfl_xor_sync(0xffffffffu, ss, off);
    if (lane == g) kss = ss;
  }
  mn = make_float4(0,0,0,0);
#pragma unroll
  for (int g = 0; g < 8; g++) {
    rows[g] = *(const float4*)(q + base + ((size_t)g*P_ << 7));
    mn.x+=rows[g].x; mn.y+=rows[g].y; mn.z+=rows[g].z; mn.w+=rows[g].w;
  }
  mn.x*=0.125f; mn.y*=0.125f; mn.z*=0.125f; mn.w*=0.125f;
  *(float4*)(g_qrep + rbase) = mn;
#pragma unroll
  for (int g = 0; g < 8; g++) {
    float dx=rows[g].x-mn.x, dy=rows[g].y-mn.y, dz=rows[g].z-mn.z, dw=rows[g].w-mn.w;
    float ss = dx*dx + dy*dy + dz*dz + dw*dw;
#pragma unroll
    for (int off = 16; off; off >>= 1) ss += __shfl_xor_sync(0xffffffffu, ss, off);
    if (lane == 8 + g) qss = ss;
  }
  mn = make_float4(0,0,0,0);
#pragma unroll
  for (int g = 0; g < 8; g++) {
    float4 r = *(const float4*)(v + base + ((size_t)g*P_ << 7));
    mn.x+=r.x; mn.y+=r.y; mn.z+=r.z; mn.w+=r.w;
  }
  mn.x*=0.125f; mn.y*=0.125f; mn.z*=0.125f; mn.w*=0.125f;
  *(float4*)(g_vmean + rbase) = mn;

  if (lane < 16) {
    int t = lane >> 3, g = lane & 7;
    float ss = t ? qss : kss;
    unsigned r = (unsigned)(bh*8192 + g*1024 + j);
    uint32_t rk0, rk1, o0, o1;
    threefry2x32(0u, 42u, 0u, (uint32_t)t, rk0, rk1);
    threefry2x32(rk0, rk1, 0u, r, o0, o1);
    uint32_t bits = o0 ^ o1;
    float u = __uint_as_float((bits >> 9) | 0x3f800000u) - 1.0f;
    if (u <= 0.0f) u = TINY_F;
    float gum = -logf(-logf(u));
    float score = logf(sqrtf(ss) * 100.0f + EPS_F) + gum;
    (t ? g_score_q : g_score_k)[r] = score;
  }
}

// ---------------- top-34 ----------------
__global__ void __launch_bounds__(256) topk_kernel() {
  int grp = blockIdx.x;
  int t   = blockIdx.y;
  float* sc = (t ? g_score_q : g_score_k) + (size_t)grp * P_;
  int*  out = (t ? g_qidx    : g_kidx   ) + (size_t)grp * MK_;
  __shared__ float sv[1024];
  __shared__ float rv[256];
  __shared__ int   ri[256];
  int tid = threadIdx.x;
#pragma unroll
  for (int r = 0; r < 4; r++) sv[tid + 256*r] = sc[tid + 256*r];
  __syncthreads();
  for (int it = 0; it < MK_; it++) {
    float bv = -INFINITY; int bi = 0x7fffffff;
#pragma unroll
    for (int r = 0; r < 4; r++) {
      int i = tid + 256*r;
      float vv = sv[i];
      if (vv > bv || (vv == bv && i < bi)) { bv = vv; bi = i; }
    }
    rv[tid] = bv; ri[tid] = bi;
    __syncthreads();
    for (int s = 128; s; s >>= 1) {
      if (tid < s) {
        float vv = rv[tid+s]; int i2 = ri[tid+s];
        if (vv > rv[tid] || (vv == rv[tid] && i2 < ri[tid])) { rv[tid]=vv; ri[tid]=i2; }
      }
      __syncthreads();
    }
    if (tid == 0) { out[it] = ri[0]; sv[ri[0]] = -INFINITY; }
    __syncthreads();
  }
}

// ---------------- gathers ----------------
__global__ void __launch_bounds__(256) gather_kernel(const float* __restrict__ q,
                                                     const float* __restrict__ k,
                                                     const float* __restrict__ v) {
  unsigned wi = (blockIdx.x * 256u + threadIdx.x) >> 5;
  int lane = threadIdx.x & 31;
  if (wi >= (unsigned)(BH_*S_)) return;
  int bh = wi / S_;
  int rr = wi % S_;
  int g = rr / MK_, tt = rr % MK_;
  int kj = g_kidx[(bh*G_+g)*MK_+tt];
  int qj = g_qidx[(bh*G_+g)*MK_+tt];
  size_t srck = ((size_t)bh*NTOK + g*P_ + kj) << 7;
  size_t srcq = ((size_t)bh*NTOK + g*P_ + qj) << 7;
  size_t dst  = ((size_t)wi << 7) + lane*4;
  *(float4*)(g_ksub    + dst) = *(const float4*)(k + srck + lane*4);
  *(float4*)(g_vsub    + dst) = *(const float4*)(v + srck + lane*4);
  *(float4*)(g_krepsub + dst) = *(const float4*)(g_krep + (((size_t)bh*P_ + kj) << 7) + lane*4);
  *(float4*)(g_qsub    + dst) = *(const float4*)(q + srcq + lane*4);
}

// ---------------- bf16x3 mma flash attention, P in registers ----------------
// warp (wq,wk): q rows wq*16..+16, keys wk*32..+32 per 64-key tile; partial O
// summed across wk at the end via smem.
__global__ void __launch_bounds__(256, 2)
attn_bf16_kernel(const float* __restrict__ kin, const float* __restrict__ vin) {
  extern __shared__ uint32_t su[];
  uint32_t* Qh = su + U_QH; uint32_t* Ql = su + U_QL;
  uint32_t* Kh = su + U_KH; uint32_t* Kl = su + U_KL;
  uint32_t* Vth = su + U_VH; uint32_t* Vtl = su + U_VL;

  int tid = threadIdx.x;
  int w = tid >> 5, lane = tid & 31;
  int gr = lane >> 2, gc = lane & 3;
  int wq = w >> 1, wk = w & 1;
  int cx3 = gr & 3;

  int bh = blockIdx.x / 88;
  int j  = blockIdx.x % 88;
  int mode, qb, sp = 0;
  if (j < 40) { mode = 3; sp = j / 5; qb = j % 5; }
  else { mode = (j - 40) >> 4; qb = (j - 40) & 15; }

  const float *Qs, *Ks, *Vs; float *dO, *dL;
  int nq, ke, ntile, k0;
  if (mode == 0) { Qs=g_qrep+(size_t)bh*P_*D_; Ks=g_krep+(size_t)bh*P_*D_;  Vs=g_vmean+(size_t)bh*P_*D_;
                   nq=P_; ke=P_; ntile=16; k0=0; dO=g_attn1; dL=g_lse1; }
  else if (mode==1){Qs=g_qrep+(size_t)bh*P_*D_; Ks=g_krepsub+(size_t)bh*S_*D_; Vs=g_vsub+(size_t)bh*S_*D_;
                   nq=P_; ke=S_; ntile=5; k0=0; dO=g_adel; dL=g_ldel; }
  else if (mode==2){Qs=g_qrep+(size_t)bh*P_*D_; Ks=g_ksub+(size_t)bh*S_*D_;  Vs=g_vsub+(size_t)bh*S_*D_;
                   nq=P_; ke=S_; ntile=5; k0=0; dO=g_aadd; dL=g_ladd; }
  else           { Qs=g_qsub+(size_t)bh*S_*D_; Ks=kin+(size_t)bh*NTOK*D_;   Vs=vin+(size_t)bh*NTOK*D_;
                   nq=S_; k0=sp*1024; ke=k0+1024; ntile=16; dO=0; dL=0; }
  int q0 = qb * 64;

  // ---- stage Q hi/lo ----
#pragma unroll
  for (int t = 0; t < 8; t++) {
    int lin = tid + t*256;
    int row = lin >> 5, c4 = lin & 31;
    int gq = q0 + row; if (gq > nq-1) gq = nq-1;
    float4 v = *(const float4*)(Qs + ((size_t)gq << 7) + c4*4);
    v.x*=SCALE_F; v.y*=SCALE_F; v.z*=SCALE_F; v.w*=SCALE_F;
    uint32_t hp0,lp0,hp1,lp1;
    split2(v.x, v.y, hp0, lp0);
    split2(v.z, v.w, hp1, lp1);
    int r7 = row & 7;
    int j0 = 2*c4, j1 = j0+1;
    int col0 = (((j0>>3) ^ r7)<<3) + ((j0&3)<<1) + ((j0>>2)&1);
    int col1 = (((j1>>3) ^ r7)<<3) + ((j1&3)<<1) + ((j1>>2)&1);
    Qh[row*64+col0]=hp0; Ql[row*64+col0]=lp0;
    Qh[row*64+col1]=hp1; Ql[row*64+col1]=lp1;
  }

  float oacc[16][4];
#pragma unroll
  for (int n=0;n<16;n++)
#pragma unroll
    for (int t=0;t<4;t++) oacc[n][t]=0.f;
  float psum[2] = {0.f, 0.f};

  int r0 = wq*16 + gr;

  for (int tile = 0; tile < ntile; tile++) {
    int kb = k0 + tile*64;
    __syncthreads();
#pragma unroll
    for (int t = 0; t < 8; t++) {
      int lin = tid + t*256;
      int row = lin >> 5, c4 = lin & 31;
      int gk = kb + row;
      float4 v = make_float4(0,0,0,0);
      if (gk < ke) v = *(const float4*)(Ks + ((size_t)gk << 7) + c4*4);
      uint32_t hp0,lp0,hp1,lp1;
      split2(v.x, v.y, hp0, lp0);
      split2(v.z, v.w, hp1, lp1);
      int r7 = row & 7;
      int j0 = 2*c4, j1 = j0+1;
      int col0 = (((j0>>3) ^ r7)<<3) + ((j0&3)<<1) + ((j0>>2)&1);
      int col1 = (((j1>>3) ^ r7)<<3) + ((j1&3)<<1) + ((j1>>2)&1);
      Kh[row*64+col0]=hp0; Kl[row*64+col0]=lp0;
      Kh[row*64+col1]=hp1; Kl[row*64+col1]=lp1;
    }
#pragma unroll
    for (int t = 0; t < 4; t++) {
      int lin = tid + t*256;
      int kp = lin & 31, dg = lin >> 5;
      int d0 = dg*4;
      int ka = kb + 2*kp;
      float4 va = make_float4(0,0,0,0), vb = va;
      if (ka   < ke) va = *(const float4*)(Vs + ((size_t)ka << 7) + d0);
      if (ka+1 < ke) vb = *(const float4*)(Vs + ((size_t)(ka+1) << 7) + d0);
      int cc = kp>>3, gg = kp&3, hh = (kp>>2)&1;
      uint32_t hp, lp;
      split2(va.x, vb.x, hp, lp);
      Vth[(d0+0)*32 + (((cc^0)<<3)+(gg<<1)+hh)] = hp; Vtl[(d0+0)*32 + (((cc^0)<<3)+(gg<<1)+hh)] = lp;
      split2(va.y, vb.y, hp, lp);
      Vth[(d0+1)*32 + (((cc^1)<<3)+(gg<<1)+hh)] = hp; Vtl[(d0+1)*32 + (((cc^1)<<3)+(gg<<1)+hh)] = lp;
      split2(va.z, vb.z, hp, lp);
      Vth[(d0+2)*32 + (((cc^2)<<3)+(gg<<1)+hh)] = hp; Vtl[(d0+2)*32 + (((cc^2)<<3)+(gg<<1)+hh)] = lp;
      split2(va.w, vb.w, hp, lp);
      Vth[(d0+3)*32 + (((cc^3)<<3)+(gg<<1)+hh)] = hp; Vtl[(d0+3)*32 + (((cc^3)<<3)+(gg<<1)+hh)] = lp;
    }
    __syncthreads();

    // ---- S = Q K^T (16q x 32k per warp, 3-pass) ----
    float sacc[4][4];
#pragma unroll
    for (int n=0;n<4;n++)
#pragma unroll
      for (int t=0;t<4;t++) sacc[n][t]=0.f;
#pragma unroll
    for (int c = 0; c < 8; c++) {
      int cq = ((c ^ gr) << 3) + (gc << 1);
      uint2 a0h = *(const uint2*)(Qh + (r0  )*64 + cq);
      uint2 a1h = *(const uint2*)(Qh + (r0+8)*64 + cq);
      uint2 a0l = *(const uint2*)(Ql + (r0  )*64 + cq);
      uint2 a1l = *(const uint2*)(Ql + (r0+8)*64 + cq);
      uint32_t Ah[4] = {a0h.x, a1h.x, a0h.y, a1h.y};
      uint32_t Al[4] = {a0l.x, a1l.x, a0l.y, a1l.y};
#pragma unroll
      for (int nn = 0; nn < 4; nn++) {
        int nb = wk*32 + nn*8 + gr;
        uint2 bh2 = *(const uint2*)(Kh + nb*64 + cq);
        uint2 bl2 = *(const uint2*)(Kl + nb*64 + cq);
        MMAB(sacc[nn], Ah, bh2.x, bh2.y);
        MMAB(sacc[nn], Ah, bl2.x, bl2.y);
        MMAB(sacc[nn], Al, bh2.x, bh2.y);
      }
    }

    // ---- exp in registers -> P fragments (no smem) ----
    // natural fill IS the A-fragment order: [0]=(gr,blk0) [1]=(gr+8,blk0)
    // [2]=(gr,blk1) [3]=(gr+8,blk1)  -- no permutation needed.
    uint32_t Phi[2][4], Plo[2][4];
#pragma unroll
    for (int kc = 0; kc < 2; kc++) {
#pragma unroll
      for (int hh = 0; hh < 2; hh++) {
        int nn = 2*kc + hh;
        int colb = kb + wk*32 + nn*8 + 2*gc;
        float p0 = (colb   < ke) ? __expf(sacc[nn][0]) : 0.f;
        float p1 = (colb+1 < ke) ? __expf(sacc[nn][1]) : 0.f;
        float p2 = (colb   < ke) ? __expf(sacc[nn][2]) : 0.f;
        float p3 = (colb+1 < ke) ? __expf(sacc[nn][3]) : 0.f;
        psum[0] += p0 + p1;
        psum[1] += p2 + p3;
        split2(p0, p1, Phi[kc][2*hh+0], Plo[kc][2*hh+0]);
        split2(p2, p3, Phi[kc][2*hh+1], Plo[kc][2*hh+1]);
      }
    }

    // ---- O += P V (partial over this warp's 32 keys, 3-pass) ----
#pragma unroll
    for (int kc = 0; kc < 2; kc++) {
      int c2 = wk*2 + kc;
      int cp = (((c2 ^ cx3) & 3) << 3) + (gc << 1);
#pragma unroll
      for (int n = 0; n < 16; n++) {
        int dn = n*8 + gr;
        uint2 vh = *(const uint2*)(Vth + dn*32 + cp);
        uint2 vl = *(const uint2*)(Vtl + dn*32 + cp);
        MMAB(oacc[n], Phi[kc], vh.x, vh.y);
        MMAB(oacc[n], Phi[kc], vl.x, vl.y);
        MMAB(oacc[n], Plo[kc], vh.x, vh.y);
      }
    }
  }

  // ---- cross-wk reduction + epilogue ----
  psum[0] += __shfl_xor_sync(0xffffffffu, psum[0], 1);
  psum[0] += __shfl_xor_sync(0xffffffffu, psum[0], 2);
  psum[1] += __shfl_xor_sync(0xffffffffu, psum[1], 1);
  psum[1] += __shfl_xor_sync(0xffffffffu, psum[1], 2);
  __syncthreads();
  float* OX  = (float*)su;               // 64 x 132 (aliases dead Q/K head)
  float* red = (float*)(su + U_VH);      // 2 x 64   (aliases dead V)
  if (wk == 1) {
#pragma unroll
    for (int n = 0; n < 16; n++) {
      int col = n*8 + 2*gc;
      *(float2*)(OX + (r0  )*132 + col) = make_float2(oacc[n][0], oacc[n][1]);
      *(float2*)(OX + (r0+8)*132 + col) = make_float2(oacc[n][2], oacc[n][3]);
    }
  }
  if (gc == 0) {
    red[wk*64 + r0]     = psum[0];
    red[wk*64 + r0 + 8] = psum[1];
  }
  __syncthreads();
  if (wk == 0) {
    float L0 = red[r0]     + red[64 + r0];
    float L1 = red[r0 + 8] + red[64 + r0 + 8];
#pragma unroll
    for (int n = 0; n < 16; n++) {
      int col = n*8 + 2*gc;
      float2 x0 = *(const float2*)(OX + (r0  )*132 + col);
      float2 x1 = *(const float2*)(OX + (r0+8)*132 + col);
      oacc[n][0] += x0.x; oacc[n][1] += x0.y;
      oacc[n][2] += x1.x; oacc[n][3] += x1.y;
    }
    if (mode < 3) {
      float iv0 = 1.0f / L0, iv1 = 1.0f / L1;
#pragma unroll
      for (int n = 0; n < 16; n++) {
        int col = n*8 + 2*gc;
        *(float2*)(dO + (((size_t)bh*nq + q0 + r0  ) << 7) + col) =
            make_float2(oacc[n][0]*iv0, oacc[n][1]*iv0);
        *(float2*)(dO + (((size_t)bh*nq + q0 + r0+8) << 7) + col) =
            make_float2(oacc[n][2]*iv1, oacc[n][3]*iv1);
      }
      if (gc == 0) {
        dL[(size_t)bh*nq + q0 + r0]     = logf(L0);
        dL[(size_t)bh*nq + q0 + r0 + 8] = logf(L1);
      }
    } else {
      size_t pb = (size_t)(sp*BH_ + bh)*320 + q0;
#pragma unroll
      for (int n = 0; n < 16; n++) {
        int col = n*8 + 2*gc;
        *(float2*)(g_part_o + ((pb + r0  ) << 7) + col) = make_float2(oacc[n][0], oacc[n][1]);
        *(float2*)(g_part_o + ((pb + r0+8) << 7) + col) = make_float2(oacc[n][2], oacc[n][3]);
      }
      if (gc == 0) {
        g_part_l[pb + r0]     = L0;
        g_part_l[pb + r0 + 8] = L1;
      }
    }
  }
}

// ---------------- p2 merge ----------------
__global__ void __launch_bounds__(256) merge3_kernel() {
  int bh = blockIdx.y;
  int w = threadIdx.x >> 5, lane = threadIdx.x & 31;
  int row = blockIdx.x*8 + w;
  if (row >= S_) return;
  float L = 0.f;
  float4 o = make_float4(0,0,0,0);
#pragma unroll
  for (int s = 0; s < 8; s++) {
    size_t ri = (size_t)(s*BH_ + bh)*320 + row;
    L += g_part_l[ri];
    float4 po = *(const float4*)(g_part_o + (ri << 7) + lane*4);
    o.x += po.x; o.y += po.y; o.z += po.z; o.w += po.w;
  }
  float inv = 1.0f / L;
  o.x*=inv; o.y*=inv; o.z*=inv; o.w*=inv;
  *(float4*)(g_a2 + (((size_t)bh*S_ + row) << 7) + lane*4) = o;
  if (lane == 0) g_l2[(size_t)bh*S_ + row] = logf(L);
}

// ---------------- p1 combine + broadcast ----------------
__global__ void __launch_bounds__(256) combine_kernel(float* __restrict__ out, int has_lse) {
  unsigned wi = (blockIdx.x * 256u + threadIdx.x) >> 5;
  int lane = threadIdx.x & 31;
  int bh = wi >> 10, j = wi & 1023;
  float l1 = g_lse1[wi] + LN8_F;
  float ld = g_ldel[wi];
  float la = g_ladd[wi];
  float c1 = expf(ld - l1);
  float inv1 = 1.0f / (1.0f - c1);
  float lp1 = l1 + log1pf(-c1);
  float c2 = 1.0f / (1.0f + expf(la - lp1));
  float lse = fmaxf(lp1, la) + log1pf(expf(-fabsf(lp1 - la)));
  size_t off = ((size_t)wi << 7) + lane*4;
  float4 a0 = *(const float4*)(g_attn1 + off);
  float4 ad = *(const float4*)(g_adel + off);
  float4 aa = *(const float4*)(g_aadd + off);
  float4 r;
  float c2b = 1.0f - c2;
  r.x = c2*((a0.x - c1*ad.x)*inv1) + c2b*aa.x;
  r.y = c2*((a0.y - c1*ad.y)*inv1) + c2b*aa.y;
  r.z = c2*((a0.z - c1*ad.z)*inv1) + c2b*aa.z;
  r.w = c2*((a0.w - c1*ad.w)*inv1) + c2b*aa.w;
  float* outl = out + (size_t)BH_*NTOK*D_;
#pragma unroll
  for (int g = 0; g < G_; g++) {
    size_t orow = (size_t)bh*NTOK + g*P_ + j;
    *(float4*)(out + (orow << 7) + lane*4) = r;
    if (lane == 0 && has_lse) outl[orow] = lse;
  }
}

// ---------------- p2 scatter ----------------
__global__ void __launch_bounds__(256) scatter_kernel(float* __restrict__ out, int has_lse) {
  unsigned wi = (blockIdx.x * 256u + threadIdx.x) >> 5;
  int lane = threadIdx.x & 31;
  if (wi >= (unsigned)(BH_*S_)) return;
  int bh = wi / S_;
  int rr = wi % S_;
  int g = rr / MK_, tt = rr % MK_;
  int qj = g_qidx[(bh*G_+g)*MK_+tt];
  size_t orow = (size_t)bh*NTOK + g*P_ + qj;
  float4 a = *(const float4*)(g_a2 + ((size_t)wi << 7) + lane*4);
  *(float4*)(out + (orow << 7) + lane*4) = a;
  if (lane == 0 && has_lse) out[(size_t)BH_*NTOK*D_ + orow] = g_l2[wi];
}

// ---------------- launch ----------------
extern "C" void kernel_launch(void* const* d_in, const int* in_sizes, int n_in,
                              void* d_out, int out_size) {
  const float* q = (const float*)d_in[0];
  const float* k = (const float*)d_in[1];
  const float* v = (const float*)d_in[2];
  float* out = (float*)d_out;
  int has_lse = (out_size >= BH_*NTOK*(D_ + 1)) ? 1 : 0;

  cudaFuncSetAttribute(attn_bf16_kernel,
                       cudaFuncAttributeMaxDynamicSharedMemorySize, SMEM_B);

  prep_kernel  <<<4096, 256>>>(q, k, v);
  topk_kernel  <<<dim3(BH_*G_, 2), 256>>>();
  gather_kernel<<<(BH_*S_*32 + 255)/256, 256>>>(q, k, v);

  attn_bf16_kernel<<<2816, 256, SMEM_B>>>(k, v);
  merge3_kernel <<<dim3((S_+7)/8, BH_), 256>>>();

  combine_kernel<<<(BH_*P_*32)/256, 256>>>(out, has_lse);
  scatter_kernel<<<(BH_*S_*32 + 255)/256, 256>>>(out, has_lse);
}